// round 2
// baseline (speedup 1.0000x reference)
#include <cuda_runtime.h>
#include <math.h>

#define BB 4
#define NN 2048
#define KNN 20
#define CSTR 963
#define EPSV 1e-5f
#define NCHUNK 32
#define ROWS_PER_CHUNK ((BB*NN)/NCHUNK)   // 256

// ---------------- scratch (device globals; no allocation allowed) ----------------
__device__ float g_F[(size_t)BB*NN*CSTR];      // concat features, layout [b][n][c]
__device__ float g_D[(size_t)BB*NN*NN];        // pairwise distances per batch
__device__ int   g_idx[(size_t)BB*NN*KNN];     // knn indices
__device__ float g_U[(size_t)BB*NN*512];       // U[b][m][o]
__device__ float g_V[(size_t)BB*NN*512];       // V[b][n][o]
__device__ float g_pS[(size_t)BB*NN*512];      // per-(b,n) partial sums over k
__device__ float g_pSS[(size_t)BB*NN*512];     // per-(b,n) partial sumsq over k
__device__ float g_cS[NCHUNK*2048];
__device__ float g_cSS[NCHUNK*2048];
__device__ float g_cMax[NCHUNK*2048];
__device__ float g_x2[BB*NN];
__device__ float g_scale[2048];
__device__ float g_bias[2048];
__device__ float g_Wd[512*256];
__device__ float g_HT[(size_t)BB*NN*2048];     // h transposed: [b][n][o]
__device__ float g_p[BB*2048];
__device__ float g_z6[BB*2048];
__device__ float g_z7[BB*4096];

// ---------------- generic NT SGEMM: C[i,j] = sum_k A[i,k]*B[j,k] ----------------
// distMode: C = sq[i] + sq[j] - 2*acc  (pairwise squared distances)
__global__ void sgemm_nt(const float* __restrict__ A, int lda, size_t sA,
                         const float* __restrict__ B, int ldb, size_t sB,
                         float* __restrict__ C, int ldc, size_t sC,
                         int M, int N, int K,
                         const float* __restrict__ sq, int distMode)
{
    __shared__ float As[16][64];
    __shared__ float Bs[16][64];
    int bz = blockIdx.z;
    A += (size_t)bz * sA;
    B += (size_t)bz * sB;
    C += (size_t)bz * sC;
    const float* sqb = sq ? (sq + (size_t)bz * NN) : (const float*)0;

    int tid = threadIdx.y * 16 + threadIdx.x;
    int row0 = blockIdx.y * 64;
    int col0 = blockIdx.x * 64;

    float acc[4][4];
#pragma unroll
    for (int i = 0; i < 4; i++)
#pragma unroll
        for (int j = 0; j < 4; j++) acc[i][j] = 0.f;

    for (int k0 = 0; k0 < K; k0 += 16) {
#pragma unroll
        for (int e = 0; e < 4; e++) {
            int idx = tid + e * 256;
            int r  = idx >> 4;
            int kk = idx & 15;
            int gk = k0 + kk;
            int gr = row0 + r;
            As[kk][r] = (gr < M && gk < K) ? A[(size_t)gr * lda + gk] : 0.f;
            int gc = col0 + r;
            Bs[kk][r] = (gc < N && gk < K) ? B[(size_t)gc * ldb + gk] : 0.f;
        }
        __syncthreads();
#pragma unroll
        for (int kk = 0; kk < 16; kk++) {
            float4 av = *(const float4*)&As[kk][threadIdx.y * 4];
            float4 bv = *(const float4*)&Bs[kk][threadIdx.x * 4];
            float a[4] = {av.x, av.y, av.z, av.w};
            float bb[4] = {bv.x, bv.y, bv.z, bv.w};
#pragma unroll
            for (int i = 0; i < 4; i++)
#pragma unroll
                for (int j = 0; j < 4; j++)
                    acc[i][j] += a[i] * bb[j];
        }
        __syncthreads();
    }

#pragma unroll
    for (int i = 0; i < 4; i++) {
        int r = row0 + threadIdx.y * 4 + i;
        if (r >= M) continue;
#pragma unroll
        for (int j = 0; j < 4; j++) {
            int c = col0 + threadIdx.x * 4 + j;
            if (c >= N) continue;
            float v = acc[i][j];
            if (distMode) v = sqb[r] + sqb[c] - 2.f * v;
            C[(size_t)r * ldc + c] = v;
        }
    }
}

// ---------------- helpers ----------------
__global__ void k_transpose_in(const float* __restrict__ x) {
    int i = blockIdx.x * blockDim.x + threadIdx.x;
    if (i >= BB * NN) return;
    int b = i / NN, n = i % NN;
    float* dst = g_F + (size_t)i * CSTR;
    dst[0] = x[(size_t)b * 3 * NN + 0 * NN + n];
    dst[1] = x[(size_t)b * 3 * NN + 1 * NN + n];
    dst[2] = x[(size_t)b * 3 * NN + 2 * NN + n];
}

__global__ void k_sqnorm(int off, int C) {
    int i = blockIdx.x * blockDim.x + threadIdx.x;
    if (i >= BB * NN) return;
    const float* row = g_F + (size_t)i * CSTR + off;
    float s = 0.f;
    for (int c = 0; c < C; c++) { float v = row[c]; s += v * v; }
    g_x2[i] = s;
}

__global__ void k_wdiff(const float* __restrict__ w, int C, int O) {
    int i = blockIdx.x * blockDim.x + threadIdx.x;
    if (i >= O * C) return;
    int o = i / C, c = i % C;
    g_Wd[i] = w[(size_t)o * 2 * C + C + c] - w[(size_t)o * 2 * C + c];
}

// one warp per row: local top-20 insertion sort + warp merge (selects the SET of 20 smallest)
__global__ void k_topk() {
    int gw = (blockIdx.x * blockDim.x + threadIdx.x) >> 5;
    int lane = threadIdx.x & 31;
    if (gw >= BB * NN) return;
    const float* row = g_D + (size_t)gw * NN;
    float bd[KNN];
    int bi[KNN];
#pragma unroll
    for (int i = 0; i < KNN; i++) { bd[i] = INFINITY; bi[i] = 0; }
    for (int m = lane; m < NN; m += 32) {
        float d = row[m];
        if (d < bd[KNN - 1]) {
            int pos = KNN - 1;
            while (pos > 0 && bd[pos - 1] > d) {
                bd[pos] = bd[pos - 1]; bi[pos] = bi[pos - 1]; pos--;
            }
            bd[pos] = d; bi[pos] = m;
        }
    }
    int ptr = 0;
    int* out = g_idx + (size_t)gw * KNN;
    for (int t = 0; t < KNN; t++) {
        float myv = (ptr < KNN) ? bd[ptr] : INFINITY;
        float bv = myv; int bl = lane;
#pragma unroll
        for (int off = 16; off; off >>= 1) {
            float ov = __shfl_down_sync(0xffffffffu, bv, off);
            int   ol = __shfl_down_sync(0xffffffffu, bl, off);
            if (ov < bv) { bv = ov; bl = ol; }
        }
        bl = __shfl_sync(0xffffffffu, bl, 0);
        int myi = (ptr < KNN) ? bi[ptr] : 0;
        int wi = __shfl_sync(0xffffffffu, myi, bl);
        if (lane == bl) ptr++;
        if (lane == 0) out[t] = wi;
    }
}

// gather 20 neighbor rows of U, reduce max / sum / sumsq over k
__global__ void k_edge_reduce(int outOff, int O) {
    int n = blockIdx.x, b = blockIdx.y;
    __shared__ int sidx[KNN];
    size_t row = (size_t)b * NN + n;
    if (threadIdx.x < KNN) sidx[threadIdx.x] = g_idx[row * KNN + threadIdx.x];
    __syncthreads();
    const float* Ub = g_U + (size_t)b * NN * O;
    const float* Vb = g_V + row * O;
    for (int o = threadIdx.x; o < O; o += blockDim.x) {
        float v = Vb[o];
        float mx = -INFINITY, s = 0.f, ss = 0.f;
#pragma unroll
        for (int j = 0; j < KNN; j++) {
            float u = Ub[(size_t)sidx[j] * O + o] + v;
            mx = fmaxf(mx, u);
            s += u; ss += u * u;
        }
        g_F[row * CSTR + outOff + o] = mx;   // raw max; BN+lrelu applied later
        g_pS[row * O + o]  = s;
        g_pSS[row * O + o] = ss;
    }
}

// deterministic two-stage column reductions
__global__ void k_chunk_reduce(int O) {
    int o = blockIdx.x * blockDim.x + threadIdx.x;
    int ch = blockIdx.y;
    if (o >= O) return;
    int r0 = ch * ROWS_PER_CHUNK;
    float s = 0.f, ss = 0.f;
    for (int r = r0; r < r0 + ROWS_PER_CHUNK; r++) {
        s  += g_pS[(size_t)r * O + o];
        ss += g_pSS[(size_t)r * O + o];
    }
    g_cS[ch * O + o] = s;
    g_cSS[ch * O + o] = ss;
}

__global__ void k_edge_stats(const float* __restrict__ g, const float* __restrict__ bet, int O) {
    int o = blockIdx.x * blockDim.x + threadIdx.x;
    if (o >= O) return;
    double s = 0.0, ss = 0.0;
    for (int ch = 0; ch < NCHUNK; ch++) { s += (double)g_cS[ch * O + o]; ss += (double)g_cSS[ch * O + o]; }
    double cnt = (double)BB * NN * KNN;
    double m = s / cnt;
    double var = ss / cnt - m * m;
    float sc = g[o] * rsqrtf((float)var + EPSV);
    g_scale[o] = sc;
    g_bias[o]  = bet[o] - (float)m * sc;
}

__global__ void k_bn_lrelu(int outOff, int O, int total) {
    int i = blockIdx.x * blockDim.x + threadIdx.x;
    if (i >= total) return;
    int o = i % O;
    size_t row = (size_t)(i / O);
    size_t p = row * CSTR + outOff + o;
    float v = g_F[p] * g_scale[o] + g_bias[o];
    g_F[p] = v > 0.f ? v : 0.2f * v;
}

// h stats: per-column sum/sumsq (over b,n) and per-(b,col) max
__global__ void k_ht_chunk() {
    int o = blockIdx.x * blockDim.x + threadIdx.x;
    int ch = blockIdx.y;
    if (o >= 2048) return;
    int r0 = ch * ROWS_PER_CHUNK;
    float s = 0.f, ss = 0.f, mx = -INFINITY;
    for (int r = r0; r < r0 + ROWS_PER_CHUNK; r++) {
        float v = g_HT[(size_t)r * 2048 + o];
        s += v; ss += v * v; mx = fmaxf(mx, v);
    }
    g_cS[ch * 2048 + o] = s;
    g_cSS[ch * 2048 + o] = ss;
    g_cMax[ch * 2048 + o] = mx;
}

__global__ void k_ht_final(const float* __restrict__ g5, const float* __restrict__ b5) {
    int o = blockIdx.x * blockDim.x + threadIdx.x;
    if (o >= 2048) return;
    double s = 0.0, ss = 0.0;
    float mb[BB];
#pragma unroll
    for (int b = 0; b < BB; b++) mb[b] = -INFINITY;
    for (int ch = 0; ch < NCHUNK; ch++) {
        s  += (double)g_cS[ch * 2048 + o];
        ss += (double)g_cSS[ch * 2048 + o];
        float m = g_cMax[ch * 2048 + o];
        int b = ch >> 3;   // 8 chunks of 256 rows per batch
        mb[b] = fmaxf(mb[b], m);
    }
    double cnt = (double)(BB * NN);
    double md = s / cnt;
    float var = (float)(ss / cnt - md * md);
    float sc = g5[o] * rsqrtf(var + EPSV);
    float bs = b5[o] - (float)md * sc;
#pragma unroll
    for (int b = 0; b < BB; b++) {
        float v = mb[b] * sc + bs;
        g_p[b * 2048 + o] = v > 0.f ? v : 0.2f * v;
    }
}

// FC + bias + BN(over batch of 4) + relu.  inB!=null => input is concat [inA(CA) ; inB(CB)]
__global__ void k_fc_bn(const float* __restrict__ W, const float* __restrict__ wb,
                        const float* __restrict__ inA, int CA,
                        const float* __restrict__ inB, int CB,
                        const float* __restrict__ g, const float* __restrict__ bet,
                        float* __restrict__ out, int O)
{
    int o = blockIdx.x;
    int Cin = CA + CB;
    const float* w = W + (size_t)o * Cin;
    float a0 = 0.f, a1 = 0.f, a2 = 0.f, a3 = 0.f;
    for (int c = threadIdx.x; c < Cin; c += blockDim.x) {
        float wv = w[c];
        float x0, x1, x2, x3;
        if (c < CA) {
            x0 = inA[c]; x1 = inA[CA + c]; x2 = inA[2 * CA + c]; x3 = inA[3 * CA + c];
        } else {
            int cc = c - CA;
            x0 = inB[cc]; x1 = inB[CB + cc]; x2 = inB[2 * CB + cc]; x3 = inB[3 * CB + cc];
        }
        a0 += wv * x0; a1 += wv * x1; a2 += wv * x2; a3 += wv * x3;
    }
    __shared__ float sm[4][256];
    sm[0][threadIdx.x] = a0; sm[1][threadIdx.x] = a1;
    sm[2][threadIdx.x] = a2; sm[3][threadIdx.x] = a3;
    __syncthreads();
    for (int st = 128; st > 0; st >>= 1) {
        if (threadIdx.x < st) {
#pragma unroll
            for (int b = 0; b < 4; b++) sm[b][threadIdx.x] += sm[b][threadIdx.x + st];
        }
        __syncthreads();
    }
    if (threadIdx.x == 0) {
        float y[4];
#pragma unroll
        for (int b = 0; b < 4; b++) y[b] = sm[b][0] + wb[o];
        float m = (y[0] + y[1] + y[2] + y[3]) * 0.25f;
        float var = 0.f;
#pragma unroll
        for (int b = 0; b < 4; b++) { float d = y[b] - m; var += d * d; }
        var *= 0.25f;
        float sc = g[o] * rsqrtf(var + EPSV);
#pragma unroll
        for (int b = 0; b < 4; b++) {
            float z = (y[b] - m) * sc + bet[o];
            out[b * O + o] = z > 0.f ? z : 0.f;
        }
    }
}

__global__ void k_fc_out(const float* __restrict__ W, const float* __restrict__ wb,
                         float* __restrict__ out)
{
    int o = blockIdx.x;  // 0..399
    const float* w = W + (size_t)o * 4096;
    float a0 = 0.f, a1 = 0.f, a2 = 0.f, a3 = 0.f;
    for (int c = threadIdx.x; c < 4096; c += blockDim.x) {
        float wv = w[c];
        a0 += wv * g_z7[c];
        a1 += wv * g_z7[4096 + c];
        a2 += wv * g_z7[2 * 4096 + c];
        a3 += wv * g_z7[3 * 4096 + c];
    }
    __shared__ float sm[4][256];
    sm[0][threadIdx.x] = a0; sm[1][threadIdx.x] = a1;
    sm[2][threadIdx.x] = a2; sm[3][threadIdx.x] = a3;
    __syncthreads();
    for (int st = 128; st > 0; st >>= 1) {
        if (threadIdx.x < st) {
#pragma unroll
            for (int b = 0; b < 4; b++) sm[b][threadIdx.x] += sm[b][threadIdx.x + st];
        }
        __syncthreads();
    }
    if (threadIdx.x == 0) {
#pragma unroll
        for (int b = 0; b < 4; b++) {
            out[b * 400 + o] = tanhf(sm[b][0] + wb[o]);
        }
    }
}

// ---------------- launch ----------------
extern "C" void kernel_launch(void* const* d_in, const int* in_sizes, int n_in,
                              void* d_out, int out_size) {
    (void)in_sizes; (void)n_in; (void)out_size;
    const float* x   = (const float*)d_in[0];
    const float* w1  = (const float*)d_in[1];
    const float* g1  = (const float*)d_in[2];
    const float* b1  = (const float*)d_in[3];
    const float* w2  = (const float*)d_in[4];
    const float* g2  = (const float*)d_in[5];
    const float* b2  = (const float*)d_in[6];
    const float* w3  = (const float*)d_in[7];
    const float* g3  = (const float*)d_in[8];
    const float* b3  = (const float*)d_in[9];
    const float* w4  = (const float*)d_in[10];
    const float* g4  = (const float*)d_in[11];
    const float* b4  = (const float*)d_in[12];
    const float* w5  = (const float*)d_in[13];
    const float* g5  = (const float*)d_in[14];
    const float* b5  = (const float*)d_in[15];
    const float* w6  = (const float*)d_in[16];
    const float* wb6 = (const float*)d_in[17];
    const float* g6  = (const float*)d_in[18];
    const float* b6  = (const float*)d_in[19];
    const float* w7  = (const float*)d_in[20];
    const float* wb7 = (const float*)d_in[21];
    const float* g7  = (const float*)d_in[22];
    const float* b7  = (const float*)d_in[23];
    const float* w8  = (const float*)d_in[24];
    const float* wb8 = (const float*)d_in[25];
    float* out = (float*)d_out;

    float *pF, *pD, *pU, *pV, *pHT, *px2, *pWd, *pp, *pz6, *pz7;
    cudaGetSymbolAddress((void**)&pF,  g_F);
    cudaGetSymbolAddress((void**)&pD,  g_D);
    cudaGetSymbolAddress((void**)&pU,  g_U);
    cudaGetSymbolAddress((void**)&pV,  g_V);
    cudaGetSymbolAddress((void**)&pHT, g_HT);
    cudaGetSymbolAddress((void**)&px2, g_x2);
    cudaGetSymbolAddress((void**)&pWd, g_Wd);
    cudaGetSymbolAddress((void**)&pp,  g_p);
    cudaGetSymbolAddress((void**)&pz6, g_z6);
    cudaGetSymbolAddress((void**)&pz7, g_z7);

    dim3 thr(16, 16);

    k_transpose_in<<<(BB * NN + 255) / 256, 256>>>(x);

    struct Layer { int inOff, C, outOff, O; const float *w, *g, *bet; };
    Layer L[4] = {
        {0,   3,   3,   64,  w1, g1, b1},
        {3,   64,  67,  128, w2, g2, b2},
        {67,  128, 195, 256, w3, g3, b3},
        {195, 256, 451, 512, w4, g4, b4},
    };

    for (int l = 0; l < 4; l++) {
        int inOff = L[l].inOff, C = L[l].C, outOff = L[l].outOff, O = L[l].O;
        const float* w = L[l].w;

        k_sqnorm<<<(BB * NN + 255) / 256, 256>>>(inOff, C);

        // pairwise distances: D = x2[n] + x2[m] - 2 * F_slice @ F_slice^T
        sgemm_nt<<<dim3(NN / 64, NN / 64, BB), thr>>>(
            pF + inOff, CSTR, (size_t)NN * CSTR,
            pF + inOff, CSTR, (size_t)NN * CSTR,
            pD, NN, (size_t)NN * NN,
            NN, NN, C, px2, 1);

        k_topk<<<(BB * NN * 32 + 255) / 256, 256>>>();

        k_wdiff<<<(O * C + 255) / 256, 256>>>(w, C, O);

        // U = X @ Wa^T   (Wa = first C cols of w, row stride 2C)
        sgemm_nt<<<dim3((O + 63) / 64, NN / 64, BB), thr>>>(
            pF + inOff, CSTR, (size_t)NN * CSTR,
            w, 2 * C, 0,
            pU, O, (size_t)NN * O,
            NN, O, C, (const float*)0, 0);
        // V = X @ (Wb-Wa)^T
        sgemm_nt<<<dim3((O + 63) / 64, NN / 64, BB), thr>>>(
            pF + inOff, CSTR, (size_t)NN * CSTR,
            pWd, C, 0,
            pV, O, (size_t)NN * O,
            NN, O, C, (const float*)0, 0);

        int ethreads = (O < 256) ? O : 256;
        k_edge_reduce<<<dim3(NN, BB), ethreads>>>(outOff, O);
        k_chunk_reduce<<<dim3((O + 255) / 256, NCHUNK), 256>>>(O);
        k_edge_stats<<<(O + 255) / 256, 256>>>(L[l].g, L[l].bet, O);
        int total = BB * NN * O;
        k_bn_lrelu<<<(total + 255) / 256, 256>>>(outOff, O, total);
    }

    // h^T[b][n][o] = F[b][n][:] . w5[o][:]
    sgemm_nt<<<dim3(2048 / 64, NN / 64, BB), thr>>>(
        pF, CSTR, (size_t)NN * CSTR,
        w5, CSTR, 0,
        pHT, 2048, (size_t)NN * 2048,
        NN, 2048, CSTR, (const float*)0, 0);

    k_ht_chunk<<<dim3(8, NCHUNK), 256>>>();
    k_ht_final<<<8, 256>>>(g5, b5);

    k_fc_bn<<<2048, 256>>>(w6, wb6, pp, 2048, (const float*)0, 0, g6, b6, pz6, 2048);
    k_fc_bn<<<4096, 256>>>(w7, wb7, pz6, 2048, pp, 2048, g7, b7, pz7, 4096);
    k_fc_out<<<400, 256>>>(w8, wb8, out);
}

// round 4
// speedup vs baseline: 1.0916x; 1.0916x over previous
#include <cuda_runtime.h>
#include <math.h>

#define BB 4
#define NN 2048
#define KNN 20
#define CSTR 963
#define EPSV 1e-5f
#define NCHUNK 32
#define ROWS_PER_CHUNK ((BB*NN)/NCHUNK)   // 256

// ---------------- scratch (device globals; no allocation allowed) ----------------
__device__ float g_F[(size_t)BB*NN*CSTR];      // concat features, layout [b][n][c]
__device__ float g_D[(size_t)BB*NN*NN];        // pairwise distances per batch
__device__ int   g_idx[(size_t)BB*NN*KNN];     // knn indices
__device__ float g_U[(size_t)BB*NN*512];       // U[b][m][o]
__device__ float g_V[(size_t)BB*NN*512];       // V[b][n][o]
__device__ float g_pS[(size_t)BB*NN*512];      // per-(b,n) partial sums over k
__device__ float g_pSS[(size_t)BB*NN*512];     // per-(b,n) partial sumsq over k
__device__ float g_cS[NCHUNK*2048];
__device__ float g_cSS[NCHUNK*2048];
__device__ float g_cMax[NCHUNK*2048];
__device__ float g_x2[BB*NN];
__device__ float g_scale[2048];
__device__ float g_bias[2048];
__device__ float g_Wd[512*256];
__device__ float g_HT[(size_t)BB*NN*2048];     // h transposed: [b][n][o]
__device__ float g_p[BB*2048];
__device__ float g_z6[BB*2048];
__device__ float g_z7[BB*4096];

// ---------------- f32x2 helpers (Blackwell packed fp32 FMA) ----------------
__device__ __forceinline__ unsigned long long dup2(float a) {
    unsigned long long r;
    asm("mov.b64 %0, {%1, %1};" : "=l"(r) : "f"(a));
    return r;
}
__device__ __forceinline__ unsigned long long fma2(unsigned long long a,
                                                   unsigned long long b,
                                                   unsigned long long c) {
    unsigned long long d;
    asm("fma.rn.f32x2 %0, %1, %2, %3;" : "=l"(d) : "l"(a), "l"(b), "l"(c));
    return d;
}

// ---------------- big NT SGEMM: 128x128 tile, 8x8/thread, f32x2, double buffer --------
// Used ONLY on the continuous path (U/V/HT). C[i,j] = sum_k A[i,k]*B[j,k]
__global__ __launch_bounds__(256) void sgemm_nt_128(
        const float* __restrict__ A, int lda, size_t sA,
        const float* __restrict__ B, int ldb, size_t sB,
        float* __restrict__ C, int ldc, size_t sC,
        int M, int N, int K)
{
    __shared__ float As[2][16][128];
    __shared__ float Bs[2][16][128];

    int bz = blockIdx.z;
    A += (size_t)bz * sA;
    B += (size_t)bz * sB;
    C += (size_t)bz * sC;

    int tid = threadIdx.x;
    int tx = tid & 15, ty = tid >> 4;
    int row0 = blockIdx.y * 128;
    int col0 = blockIdx.x * 128;

    unsigned long long acc[8][4];
#pragma unroll
    for (int i = 0; i < 8; i++)
#pragma unroll
        for (int j = 0; j < 4; j++) acc[i][j] = 0ULL;

    int ntiles = (K + 15) >> 4;
    float ra[8], rb[8];

    // preload tile 0
#pragma unroll
    for (int e = 0; e < 8; e++) {
        int idx = tid + e * 256;
        int r = idx >> 4, kk = idx & 15;
        ra[e] = (row0 + r < M && kk < K) ? A[(size_t)(row0 + r) * lda + kk] : 0.f;
        rb[e] = (col0 + r < N && kk < K) ? B[(size_t)(col0 + r) * ldb + kk] : 0.f;
    }
#pragma unroll
    for (int e = 0; e < 8; e++) {
        int idx = tid + e * 256;
        int r = idx >> 4, kk = idx & 15;
        As[0][kk][r] = ra[e];
        Bs[0][kk][r] = rb[e];
    }
    __syncthreads();

    int buf = 0;
    for (int t = 0; t < ntiles; t++) {
        int k0n = (t + 1) * 16;
        if (t + 1 < ntiles) {
#pragma unroll
            for (int e = 0; e < 8; e++) {
                int idx = tid + e * 256;
                int r = idx >> 4, kk = idx & 15;
                int gk = k0n + kk;
                ra[e] = (row0 + r < M && gk < K) ? A[(size_t)(row0 + r) * lda + gk] : 0.f;
                rb[e] = (col0 + r < N && gk < K) ? B[(size_t)(col0 + r) * ldb + gk] : 0.f;
            }
        }

#pragma unroll
        for (int kk = 0; kk < 16; kk++) {
            float4 a0 = *(const float4*)&As[buf][kk][ty * 8];
            float4 a1 = *(const float4*)&As[buf][kk][ty * 8 + 4];
            ulonglong2 bv0 = *(const ulonglong2*)&Bs[buf][kk][tx * 8];
            ulonglong2 bv1 = *(const ulonglong2*)&Bs[buf][kk][tx * 8 + 4];
            unsigned long long bp[4] = {bv0.x, bv0.y, bv1.x, bv1.y};
            float av[8] = {a0.x, a0.y, a0.z, a0.w, a1.x, a1.y, a1.z, a1.w};
#pragma unroll
            for (int i = 0; i < 8; i++) {
                unsigned long long ad = dup2(av[i]);
#pragma unroll
                for (int j = 0; j < 4; j++)
                    acc[i][j] = fma2(ad, bp[j], acc[i][j]);
            }
        }

        if (t + 1 < ntiles) {
#pragma unroll
            for (int e = 0; e < 8; e++) {
                int idx = tid + e * 256;
                int r = idx >> 4, kk = idx & 15;
                As[buf ^ 1][kk][r] = ra[e];
                Bs[buf ^ 1][kk][r] = rb[e];
            }
        }
        __syncthreads();
        buf ^= 1;
    }

#pragma unroll
    for (int i = 0; i < 8; i++) {
        int r = row0 + ty * 8 + i;
        if (r >= M) continue;
#pragma unroll
        for (int j = 0; j < 4; j++) {
            int c = col0 + tx * 8 + j * 2;
            float2 v = *(float2*)&acc[i][j];
            if (c + 1 < N) {
                *(float2*)&C[(size_t)r * ldc + c] = v;
            } else if (c < N) {
                C[(size_t)r * ldc + c] = v.x;
            }
        }
    }
}

// ---------------- round-2 exact NT SGEMM (discrete path: distances; small O) ---------
__global__ void sgemm_nt(const float* __restrict__ A, int lda, size_t sA,
                         const float* __restrict__ B, int ldb, size_t sB,
                         float* __restrict__ C, int ldc, size_t sC,
                         int M, int N, int K,
                         const float* __restrict__ sq, int distMode)
{
    __shared__ float As[16][64];
    __shared__ float Bs[16][64];
    int bz = blockIdx.z;
    A += (size_t)bz * sA;
    B += (size_t)bz * sB;
    C += (size_t)bz * sC;
    const float* sqb = sq ? (sq + (size_t)bz * NN) : (const float*)0;

    int tid = threadIdx.y * 16 + threadIdx.x;
    int row0 = blockIdx.y * 64;
    int col0 = blockIdx.x * 64;

    float acc[4][4];
#pragma unroll
    for (int i = 0; i < 4; i++)
#pragma unroll
        for (int j = 0; j < 4; j++) acc[i][j] = 0.f;

    for (int k0 = 0; k0 < K; k0 += 16) {
#pragma unroll
        for (int e = 0; e < 4; e++) {
            int idx = tid + e * 256;
            int r  = idx >> 4;
            int kk = idx & 15;
            int gk = k0 + kk;
            int gr = row0 + r;
            As[kk][r] = (gr < M && gk < K) ? A[(size_t)gr * lda + gk] : 0.f;
            int gc = col0 + r;
            Bs[kk][r] = (gc < N && gk < K) ? B[(size_t)gc * ldb + gk] : 0.f;
        }
        __syncthreads();
#pragma unroll
        for (int kk = 0; kk < 16; kk++) {
            float4 av = *(const float4*)&As[kk][threadIdx.y * 4];
            float4 bv = *(const float4*)&Bs[kk][threadIdx.x * 4];
            float a[4] = {av.x, av.y, av.z, av.w};
            float bb[4] = {bv.x, bv.y, bv.z, bv.w};
#pragma unroll
            for (int i = 0; i < 4; i++)
#pragma unroll
                for (int j = 0; j < 4; j++)
                    acc[i][j] += a[i] * bb[j];
        }
        __syncthreads();
    }

#pragma unroll
    for (int i = 0; i < 4; i++) {
        int r = row0 + threadIdx.y * 4 + i;
        if (r >= M) continue;
#pragma unroll
        for (int j = 0; j < 4; j++) {
            int c = col0 + threadIdx.x * 4 + j;
            if (c >= N) continue;
            float v = acc[i][j];
            if (distMode) v = sqb[r] + sqb[c] - 2.f * v;
            C[(size_t)r * ldc + c] = v;
        }
    }
}

// ---------------- helpers ----------------
__global__ void k_transpose_in(const float* __restrict__ x) {
    int i = blockIdx.x * blockDim.x + threadIdx.x;
    if (i >= BB * NN) return;
    int b = i / NN, n = i % NN;
    float* dst = g_F + (size_t)i * CSTR;
    dst[0] = x[(size_t)b * 3 * NN + 0 * NN + n];
    dst[1] = x[(size_t)b * 3 * NN + 1 * NN + n];
    dst[2] = x[(size_t)b * 3 * NN + 2 * NN + n];
}

__global__ void k_sqnorm(int off, int C) {
    int i = blockIdx.x * blockDim.x + threadIdx.x;
    if (i >= BB * NN) return;
    const float* row = g_F + (size_t)i * CSTR + off;
    float s = 0.f;
    for (int c = 0; c < C; c++) { float v = row[c]; s += v * v; }
    g_x2[i] = s;
}

__global__ void k_wdiff(const float* __restrict__ w, int C, int O) {
    int i = blockIdx.x * blockDim.x + threadIdx.x;
    if (i >= O * C) return;
    int o = i / C, c = i % C;
    g_Wd[i] = w[(size_t)o * 2 * C + C + c] - w[(size_t)o * 2 * C + c];
}

// round-2 exact top-k: one warp per row, strided scan, insertion sort + warp merge
__global__ void k_topk() {
    int gw = (blockIdx.x * blockDim.x + threadIdx.x) >> 5;
    int lane = threadIdx.x & 31;
    if (gw >= BB * NN) return;
    const float* row = g_D + (size_t)gw * NN;
    float bd[KNN];
    int bi[KNN];
#pragma unroll
    for (int i = 0; i < KNN; i++) { bd[i] = INFINITY; bi[i] = 0; }
    for (int m = lane; m < NN; m += 32) {
        float d = row[m];
        if (d < bd[KNN - 1]) {
            int pos = KNN - 1;
            while (pos > 0 && bd[pos - 1] > d) {
                bd[pos] = bd[pos - 1]; bi[pos] = bi[pos - 1]; pos--;
            }
            bd[pos] = d; bi[pos] = m;
        }
    }
    int ptr = 0;
    int* out = g_idx + (size_t)gw * KNN;
    for (int t = 0; t < KNN; t++) {
        float myv = (ptr < KNN) ? bd[ptr] : INFINITY;
        float bv = myv; int bl = lane;
#pragma unroll
        for (int off = 16; off; off >>= 1) {
            float ov = __shfl_down_sync(0xffffffffu, bv, off);
            int   ol = __shfl_down_sync(0xffffffffu, bl, off);
            if (ov < bv) { bv = ov; bl = ol; }
        }
        bl = __shfl_sync(0xffffffffu, bl, 0);
        int myi = (ptr < KNN) ? bi[ptr] : 0;
        int wi = __shfl_sync(0xffffffffu, myi, bl);
        if (lane == bl) ptr++;
        if (lane == 0) out[t] = wi;
    }
}

// gather 20 neighbor rows of U, reduce max / sum / sumsq over k
__global__ void k_edge_reduce(int outOff, int O) {
    int n = blockIdx.x, b = blockIdx.y;
    __shared__ int sidx[KNN];
    size_t row = (size_t)b * NN + n;
    if (threadIdx.x < KNN) sidx[threadIdx.x] = g_idx[row * KNN + threadIdx.x];
    __syncthreads();
    const float* Ub = g_U + (size_t)b * NN * O;
    const float* Vb = g_V + row * O;
    for (int o = threadIdx.x; o < O; o += blockDim.x) {
        float v = Vb[o];
        float mx = -INFINITY, s = 0.f, ss = 0.f;
#pragma unroll
        for (int j = 0; j < KNN; j++) {
            float u = Ub[(size_t)sidx[j] * O + o] + v;
            mx = fmaxf(mx, u);
            s += u; ss += u * u;
        }
        g_F[row * CSTR + outOff + o] = mx;   // raw max; BN+lrelu applied later
        g_pS[row * O + o]  = s;
        g_pSS[row * O + o] = ss;
    }
}

// deterministic two-stage column reductions
__global__ void k_chunk_reduce(int O) {
    int o = blockIdx.x * blockDim.x + threadIdx.x;
    int ch = blockIdx.y;
    if (o >= O) return;
    int r0 = ch * ROWS_PER_CHUNK;
    float s = 0.f, ss = 0.f;
    for (int r = r0; r < r0 + ROWS_PER_CHUNK; r++) {
        s  += g_pS[(size_t)r * O + o];
        ss += g_pSS[(size_t)r * O + o];
    }
    g_cS[ch * O + o] = s;
    g_cSS[ch * O + o] = ss;
}

__global__ void k_edge_stats(const float* __restrict__ g, const float* __restrict__ bet, int O) {
    int o = blockIdx.x * blockDim.x + threadIdx.x;
    if (o >= O) return;
    double s = 0.0, ss = 0.0;
    for (int ch = 0; ch < NCHUNK; ch++) { s += (double)g_cS[ch * O + o]; ss += (double)g_cSS[ch * O + o]; }
    double cnt = (double)BB * NN * KNN;
    double m = s / cnt;
    double var = ss / cnt - m * m;
    float sc = g[o] * rsqrtf((float)var + EPSV);
    g_scale[o] = sc;
    g_bias[o]  = bet[o] - (float)m * sc;
}

__global__ void k_bn_lrelu(int outOff, int O, int total) {
    int i = blockIdx.x * blockDim.x + threadIdx.x;
    if (i >= total) return;
    int o = i % O;
    size_t row = (size_t)(i / O);
    size_t p = row * CSTR + outOff + o;
    float v = g_F[p] * g_scale[o] + g_bias[o];
    g_F[p] = v > 0.f ? v : 0.2f * v;
}

// h stats: per-column sum/sumsq (over b,n) and per-(b,col) max
__global__ void k_ht_chunk() {
    int o = blockIdx.x * blockDim.x + threadIdx.x;
    int ch = blockIdx.y;
    if (o >= 2048) return;
    int r0 = ch * ROWS_PER_CHUNK;
    float s = 0.f, ss = 0.f, mx = -INFINITY;
    for (int r = r0; r < r0 + ROWS_PER_CHUNK; r++) {
        float v = g_HT[(size_t)r * 2048 + o];
        s += v; ss += v * v; mx = fmaxf(mx, v);
    }
    g_cS[ch * 2048 + o] = s;
    g_cSS[ch * 2048 + o] = ss;
    g_cMax[ch * 2048 + o] = mx;
}

__global__ void k_ht_final(const float* __restrict__ g5, const float* __restrict__ b5) {
    int o = blockIdx.x * blockDim.x + threadIdx.x;
    if (o >= 2048) return;
    double s = 0.0, ss = 0.0;
    float mb[BB];
#pragma unroll
    for (int b = 0; b < BB; b++) mb[b] = -INFINITY;
    for (int ch = 0; ch < NCHUNK; ch++) {
        s  += (double)g_cS[ch * 2048 + o];
        ss += (double)g_cSS[ch * 2048 + o];
        float m = g_cMax[ch * 2048 + o];
        int b = ch >> 3;   // 8 chunks of 256 rows per batch
        mb[b] = fmaxf(mb[b], m);
    }
    double cnt = (double)(BB * NN);
    double md = s / cnt;
    float var = (float)(ss / cnt - md * md);
    float sc = g5[o] * rsqrtf(var + EPSV);
    float bs = b5[o] - (float)md * sc;
#pragma unroll
    for (int b = 0; b < BB; b++) {
        float v = mb[b] * sc + bs;
        g_p[b * 2048 + o] = v > 0.f ? v : 0.2f * v;
    }
}

// FC + bias + BN(over batch of 4) + relu.  inB!=null => input is concat [inA(CA) ; inB(CB)]
__global__ void k_fc_bn(const float* __restrict__ W, const float* __restrict__ wb,
                        const float* __restrict__ inA, int CA,
                        const float* __restrict__ inB, int CB,
                        const float* __restrict__ g, const float* __restrict__ bet,
                        float* __restrict__ out, int O)
{
    int o = blockIdx.x;
    int Cin = CA + CB;
    const float* w = W + (size_t)o * Cin;
    float a0 = 0.f, a1 = 0.f, a2 = 0.f, a3 = 0.f;
    for (int c = threadIdx.x; c < Cin; c += blockDim.x) {
        float wv = w[c];
        float x0, x1, x2, x3;
        if (c < CA) {
            x0 = inA[c]; x1 = inA[CA + c]; x2 = inA[2 * CA + c]; x3 = inA[3 * CA + c];
        } else {
            int cc = c - CA;
            x0 = inB[cc]; x1 = inB[CB + cc]; x2 = inB[2 * CB + cc]; x3 = inB[3 * CB + cc];
        }
        a0 += wv * x0; a1 += wv * x1; a2 += wv * x2; a3 += wv * x3;
    }
    __shared__ float sm[4][256];
    sm[0][threadIdx.x] = a0; sm[1][threadIdx.x] = a1;
    sm[2][threadIdx.x] = a2; sm[3][threadIdx.x] = a3;
    __syncthreads();
    for (int st = 128; st > 0; st >>= 1) {
        if (threadIdx.x < st) {
#pragma unroll
            for (int b = 0; b < 4; b++) sm[b][threadIdx.x] += sm[b][threadIdx.x + st];
        }
        __syncthreads();
    }
    if (threadIdx.x == 0) {
        float y[4];
#pragma unroll
        for (int b = 0; b < 4; b++) y[b] = sm[b][0] + wb[o];
        float m = (y[0] + y[1] + y[2] + y[3]) * 0.25f;
        float var = 0.f;
#pragma unroll
        for (int b = 0; b < 4; b++) { float d = y[b] - m; var += d * d; }
        var *= 0.25f;
        float sc = g[o] * rsqrtf(var + EPSV);
#pragma unroll
        for (int b = 0; b < 4; b++) {
            float z = (y[b] - m) * sc + bet[o];
            out[b * O + o] = z > 0.f ? z : 0.f;
        }
    }
}

__global__ void k_fc_out(const float* __restrict__ W, const float* __restrict__ wb,
                         float* __restrict__ out)
{
    int o = blockIdx.x;  // 0..399
    const float* w = W + (size_t)o * 4096;
    float a0 = 0.f, a1 = 0.f, a2 = 0.f, a3 = 0.f;
    for (int c = threadIdx.x; c < 4096; c += blockDim.x) {
        float wv = w[c];
        a0 += wv * g_z7[c];
        a1 += wv * g_z7[4096 + c];
        a2 += wv * g_z7[2 * 4096 + c];
        a3 += wv * g_z7[3 * 4096 + c];
    }
    __shared__ float sm[4][256];
    sm[0][threadIdx.x] = a0; sm[1][threadIdx.x] = a1;
    sm[2][threadIdx.x] = a2; sm[3][threadIdx.x] = a3;
    __syncthreads();
    for (int st = 128; st > 0; st >>= 1) {
        if (threadIdx.x < st) {
#pragma unroll
            for (int b = 0; b < 4; b++) sm[b][threadIdx.x] += sm[b][threadIdx.x + st];
        }
        __syncthreads();
    }
    if (threadIdx.x == 0) {
#pragma unroll
        for (int b = 0; b < 4; b++) {
            out[b * 400 + o] = tanhf(sm[b][0] + wb[o]);
        }
    }
}

// ---------------- launch ----------------
extern "C" void kernel_launch(void* const* d_in, const int* in_sizes, int n_in,
                              void* d_out, int out_size) {
    (void)in_sizes; (void)n_in; (void)out_size;
    const float* x   = (const float*)d_in[0];
    const float* w1  = (const float*)d_in[1];
    const float* g1  = (const float*)d_in[2];
    const float* b1  = (const float*)d_in[3];
    const float* w2  = (const float*)d_in[4];
    const float* g2  = (const float*)d_in[5];
    const float* b2  = (const float*)d_in[6];
    const float* w3  = (const float*)d_in[7];
    const float* g3  = (const float*)d_in[8];
    const float* b3  = (const float*)d_in[9];
    const float* w4  = (const float*)d_in[10];
    const float* g4  = (const float*)d_in[11];
    const float* b4  = (const float*)d_in[12];
    const float* w5  = (const float*)d_in[13];
    const float* g5  = (const float*)d_in[14];
    const float* b5  = (const float*)d_in[15];
    const float* w6  = (const float*)d_in[16];
    const float* wb6 = (const float*)d_in[17];
    const float* g6  = (const float*)d_in[18];
    const float* b6  = (const float*)d_in[19];
    const float* w7  = (const float*)d_in[20];
    const float* wb7 = (const float*)d_in[21];
    const float* g7  = (const float*)d_in[22];
    const float* b7  = (const float*)d_in[23];
    const float* w8  = (const float*)d_in[24];
    const float* wb8 = (const float*)d_in[25];
    float* out = (float*)d_out;

    float *pF, *pD, *pU, *pV, *pHT, *px2, *pWd, *pp, *pz6, *pz7;
    cudaGetSymbolAddress((void**)&pF,  g_F);
    cudaGetSymbolAddress((void**)&pD,  g_D);
    cudaGetSymbolAddress((void**)&pU,  g_U);
    cudaGetSymbolAddress((void**)&pV,  g_V);
    cudaGetSymbolAddress((void**)&pHT, g_HT);
    cudaGetSymbolAddress((void**)&px2, g_x2);
    cudaGetSymbolAddress((void**)&pWd, g_Wd);
    cudaGetSymbolAddress((void**)&pp,  g_p);
    cudaGetSymbolAddress((void**)&pz6, g_z6);
    cudaGetSymbolAddress((void**)&pz7, g_z7);

    dim3 thrS(16, 16);

    k_transpose_in<<<(BB * NN + 255) / 256, 256>>>(x);

    struct Layer { int inOff, C, outOff, O; const float *w, *g, *bet; };
    Layer L[4] = {
        {0,   3,   3,   64,  w1, g1, b1},
        {3,   64,  67,  128, w2, g2, b2},
        {67,  128, 195, 256, w3, g3, b3},
        {195, 256, 451, 512, w4, g4, b4},
    };

    for (int l = 0; l < 4; l++) {
        int inOff = L[l].inOff, C = L[l].C, outOff = L[l].outOff, O = L[l].O;
        const float* w = L[l].w;

        k_sqnorm<<<(BB * NN + 255) / 256, 256>>>(inOff, C);

        // pairwise distances (DISCRETE path — bit-exact round-2 kernel)
        sgemm_nt<<<dim3(NN / 64, NN / 64, BB), thrS>>>(
            pF + inOff, CSTR, (size_t)NN * CSTR,
            pF + inOff, CSTR, (size_t)NN * CSTR,
            pD, NN, (size_t)NN * NN,
            NN, NN, C, px2, 1);

        k_topk<<<(BB * NN * 32 + 255) / 256, 256>>>();

        k_wdiff<<<(O * C + 255) / 256, 256>>>(w, C, O);

        if (O >= 128) {
            // U = X @ Wa^T  (continuous path -> fast f32x2 GEMM)
            sgemm_nt_128<<<dim3(O / 128, NN / 128, BB), 256>>>(
                pF + inOff, CSTR, (size_t)NN * CSTR,
                w, 2 * C, 0,
                pU, O, (size_t)NN * O,
                NN, O, C);
            // V = X @ (Wb-Wa)^T
            sgemm_nt_128<<<dim3(O / 128, NN / 128, BB), 256>>>(
                pF + inOff, CSTR, (size_t)NN * CSTR,
                pWd, C, 0,
                pV, O, (size_t)NN * O,
                NN, O, C);
        } else {
            sgemm_nt<<<dim3((O + 63) / 64, NN / 64, BB), thrS>>>(
                pF + inOff, CSTR, (size_t)NN * CSTR,
                w, 2 * C, 0,
                pU, O, (size_t)NN * O,
                NN, O, C, (const float*)0, 0);
            sgemm_nt<<<dim3((O + 63) / 64, NN / 64, BB), thrS>>>(
                pF + inOff, CSTR, (size_t)NN * CSTR,
                pWd, C, 0,
                pV, O, (size_t)NN * O,
                NN, O, C, (const float*)0, 0);
        }

        int ethreads = (O < 256) ? O : 256;
        k_edge_reduce<<<dim3(NN, BB), ethreads>>>(outOff, O);
        k_chunk_reduce<<<dim3((O + 255) / 256, NCHUNK), 256>>>(O);
        k_edge_stats<<<(O + 255) / 256, 256>>>(L[l].g, L[l].bet, O);
        int total = BB * NN * O;
        k_bn_lrelu<<<(total + 255) / 256, 256>>>(outOff, O, total);
    }

    // h^T[b][n][o] = F[b][n][:] . w5[o][:]   (continuous path -> fast GEMM)
    sgemm_nt_128<<<dim3(2048 / 128, NN / 128, BB), 256>>>(
        pF, CSTR, (size_t)NN * CSTR,
        w5, CSTR, 0,
        pHT, 2048, (size_t)NN * 2048,
        NN, 2048, CSTR);

    k_ht_chunk<<<dim3(8, NCHUNK), 256>>>();
    k_ht_final<<<8, 256>>>(g5, b5);

    k_fc_bn<<<2048, 256>>>(w6, wb6, pp, 2048, (const float*)0, 0, g6, b6, pz6, 2048);
    k_fc_bn<<<4096, 256>>>(w7, wb7, pz6, 2048, pp, 2048, g7, b7, pz7, 4096);
    k_fc_out<<<400, 256>>>(w8, wb8, out);
}

// round 6
// speedup vs baseline: 1.7191x; 1.5748x over previous
#include <cuda_runtime.h>
#include <math.h>

#define BB 4
#define NN 2048
#define KNN 20
#define CSTR 963
#define EPSV 1e-5f
#define NCHUNK 32
#define ROWS_PER_CHUNK ((BB*NN)/NCHUNK)   // 256

// ---------------- scratch (device globals; no allocation allowed) ----------------
__device__ float g_F[(size_t)BB*NN*CSTR];      // concat features, layout [b][n][c]
__device__ float g_D[(size_t)BB*NN*NN];        // pairwise distances per batch
__device__ int   g_idx[(size_t)BB*NN*KNN];     // knn indices
__device__ float g_U[(size_t)BB*NN*512];       // U[b][m][o]
__device__ float g_V[(size_t)BB*NN*512];       // V[b][n][o]
__device__ float g_pS[(size_t)BB*NN*512];      // per-(b,n) partial sums over k
__device__ float g_pSS[(size_t)BB*NN*512];     // per-(b,n) partial sumsq over k
__device__ float g_cS[NCHUNK*2048];
__device__ float g_cSS[NCHUNK*2048];
__device__ float g_cMax[NCHUNK*2048];
__device__ float g_x2[BB*NN];
__device__ float g_scale[2048];
__device__ float g_bias[2048];
__device__ float g_Wd[512*256];
__device__ float g_HT[(size_t)BB*NN*2048];     // h transposed: [b][n][o]
__device__ float g_p[BB*2048];
__device__ float g_z6[BB*2048];
__device__ float g_z7[BB*4096];

// ---------------- f32x2 helpers (Blackwell packed fp32 FMA) ----------------
__device__ __forceinline__ unsigned long long dup2(float a) {
    unsigned long long r;
    asm("mov.b64 %0, {%1, %1};" : "=l"(r) : "f"(a));
    return r;
}
__device__ __forceinline__ unsigned long long fma2(unsigned long long a,
                                                   unsigned long long b,
                                                   unsigned long long c) {
    unsigned long long d;
    asm("fma.rn.f32x2 %0, %1, %2, %3;" : "=l"(d) : "l"(a), "l"(b), "l"(c));
    return d;
}

// ---------------- big NT SGEMM: 128x128 tile, 8x8/thread, f32x2, double buffer --------
// Used ONLY on the continuous path (U/V/HT). C[i,j] = sum_k A[i,k]*B[j,k]
__global__ __launch_bounds__(256) void sgemm_nt_128(
        const float* __restrict__ A, int lda, size_t sA,
        const float* __restrict__ B, int ldb, size_t sB,
        float* __restrict__ C, int ldc, size_t sC,
        int M, int N, int K)
{
    __shared__ float As[2][16][128];
    __shared__ float Bs[2][16][128];

    int bz = blockIdx.z;
    A += (size_t)bz * sA;
    B += (size_t)bz * sB;
    C += (size_t)bz * sC;

    int tid = threadIdx.x;
    int tx = tid & 15, ty = tid >> 4;
    int row0 = blockIdx.y * 128;
    int col0 = blockIdx.x * 128;

    unsigned long long acc[8][4];
#pragma unroll
    for (int i = 0; i < 8; i++)
#pragma unroll
        for (int j = 0; j < 4; j++) acc[i][j] = 0ULL;

    int ntiles = (K + 15) >> 4;
    float ra[8], rb[8];

    // preload tile 0
#pragma unroll
    for (int e = 0; e < 8; e++) {
        int idx = tid + e * 256;
        int r = idx >> 4, kk = idx & 15;
        ra[e] = (row0 + r < M && kk < K) ? A[(size_t)(row0 + r) * lda + kk] : 0.f;
        rb[e] = (col0 + r < N && kk < K) ? B[(size_t)(col0 + r) * ldb + kk] : 0.f;
    }
#pragma unroll
    for (int e = 0; e < 8; e++) {
        int idx = tid + e * 256;
        int r = idx >> 4, kk = idx & 15;
        As[0][kk][r] = ra[e];
        Bs[0][kk][r] = rb[e];
    }
    __syncthreads();

    int buf = 0;
    for (int t = 0; t < ntiles; t++) {
        int k0n = (t + 1) * 16;
        if (t + 1 < ntiles) {
#pragma unroll
            for (int e = 0; e < 8; e++) {
                int idx = tid + e * 256;
                int r = idx >> 4, kk = idx & 15;
                int gk = k0n + kk;
                ra[e] = (row0 + r < M && gk < K) ? A[(size_t)(row0 + r) * lda + gk] : 0.f;
                rb[e] = (col0 + r < N && gk < K) ? B[(size_t)(col0 + r) * ldb + gk] : 0.f;
            }
        }

#pragma unroll
        for (int kk = 0; kk < 16; kk++) {
            float4 a0 = *(const float4*)&As[buf][kk][ty * 8];
            float4 a1 = *(const float4*)&As[buf][kk][ty * 8 + 4];
            ulonglong2 bv0 = *(const ulonglong2*)&Bs[buf][kk][tx * 8];
            ulonglong2 bv1 = *(const ulonglong2*)&Bs[buf][kk][tx * 8 + 4];
            unsigned long long bp[4] = {bv0.x, bv0.y, bv1.x, bv1.y};
            float av[8] = {a0.x, a0.y, a0.z, a0.w, a1.x, a1.y, a1.z, a1.w};
#pragma unroll
            for (int i = 0; i < 8; i++) {
                unsigned long long ad = dup2(av[i]);
#pragma unroll
                for (int j = 0; j < 4; j++)
                    acc[i][j] = fma2(ad, bp[j], acc[i][j]);
            }
        }

        if (t + 1 < ntiles) {
#pragma unroll
            for (int e = 0; e < 8; e++) {
                int idx = tid + e * 256;
                int r = idx >> 4, kk = idx & 15;
                As[buf ^ 1][kk][r] = ra[e];
                Bs[buf ^ 1][kk][r] = rb[e];
            }
        }
        __syncthreads();
        buf ^= 1;
    }

#pragma unroll
    for (int i = 0; i < 8; i++) {
        int r = row0 + ty * 8 + i;
        if (r >= M) continue;
#pragma unroll
        for (int j = 0; j < 4; j++) {
            int c = col0 + tx * 8 + j * 2;
            float2 v = *(float2*)&acc[i][j];
            if (c + 1 < N) {
                *(float2*)&C[(size_t)r * ldc + c] = v;
            } else if (c < N) {
                C[(size_t)r * ldc + c] = v.x;
            }
        }
    }
}

// ---------------- round-2 exact NT SGEMM (discrete path: distances; small O) ---------
__global__ void sgemm_nt(const float* __restrict__ A, int lda, size_t sA,
                         const float* __restrict__ B, int ldb, size_t sB,
                         float* __restrict__ C, int ldc, size_t sC,
                         int M, int N, int K,
                         const float* __restrict__ sq, int distMode)
{
    __shared__ float As[16][64];
    __shared__ float Bs[16][64];
    int bz = blockIdx.z;
    A += (size_t)bz * sA;
    B += (size_t)bz * sB;
    C += (size_t)bz * sC;
    const float* sqb = sq ? (sq + (size_t)bz * NN) : (const float*)0;

    int tid = threadIdx.y * 16 + threadIdx.x;
    int row0 = blockIdx.y * 64;
    int col0 = blockIdx.x * 64;

    float acc[4][4];
#pragma unroll
    for (int i = 0; i < 4; i++)
#pragma unroll
        for (int j = 0; j < 4; j++) acc[i][j] = 0.f;

    for (int k0 = 0; k0 < K; k0 += 16) {
#pragma unroll
        for (int e = 0; e < 4; e++) {
            int idx = tid + e * 256;
            int r  = idx >> 4;
            int kk = idx & 15;
            int gk = k0 + kk;
            int gr = row0 + r;
            As[kk][r] = (gr < M && gk < K) ? A[(size_t)gr * lda + gk] : 0.f;
            int gc = col0 + r;
            Bs[kk][r] = (gc < N && gk < K) ? B[(size_t)gc * ldb + gk] : 0.f;
        }
        __syncthreads();
#pragma unroll
        for (int kk = 0; kk < 16; kk++) {
            float4 av = *(const float4*)&As[kk][threadIdx.y * 4];
            float4 bv = *(const float4*)&Bs[kk][threadIdx.x * 4];
            float a[4] = {av.x, av.y, av.z, av.w};
            float bb[4] = {bv.x, bv.y, bv.z, bv.w};
#pragma unroll
            for (int i = 0; i < 4; i++)
#pragma unroll
                for (int j = 0; j < 4; j++)
                    acc[i][j] += a[i] * bb[j];
        }
        __syncthreads();
    }

#pragma unroll
    for (int i = 0; i < 4; i++) {
        int r = row0 + threadIdx.y * 4 + i;
        if (r >= M) continue;
#pragma unroll
        for (int j = 0; j < 4; j++) {
            int c = col0 + threadIdx.x * 4 + j;
            if (c >= N) continue;
            float v = acc[i][j];
            if (distMode) v = sqb[r] + sqb[c] - 2.f * v;
            C[(size_t)r * ldc + c] = v;
        }
    }
}

// ---------------- helpers ----------------
__global__ void k_transpose_in(const float* __restrict__ x) {
    int i = blockIdx.x * blockDim.x + threadIdx.x;
    if (i >= BB * NN) return;
    int b = i / NN, n = i % NN;
    float* dst = g_F + (size_t)i * CSTR;
    dst[0] = x[(size_t)b * 3 * NN + 0 * NN + n];
    dst[1] = x[(size_t)b * 3 * NN + 1 * NN + n];
    dst[2] = x[(size_t)b * 3 * NN + 2 * NN + n];
}

__global__ void k_sqnorm(int off, int C) {
    int i = blockIdx.x * blockDim.x + threadIdx.x;
    if (i >= BB * NN) return;
    const float* row = g_F + (size_t)i * CSTR + off;
    float s = 0.f;
    for (int c = 0; c < C; c++) { float v = row[c]; s += v * v; }
    g_x2[i] = s;
}

__global__ void k_wdiff(const float* __restrict__ w, int C, int O) {
    int i = blockIdx.x * blockDim.x + threadIdx.x;
    if (i >= O * C) return;
    int o = i / C, c = i % C;
    g_Wd[i] = w[(size_t)o * 2 * C + C + c] - w[(size_t)o * 2 * C + c];
}

// ---------------- exact kNN selection via 3-level radix histogram ----------------
// One 256-thread block per row. Selects the exact 20 smallest distances with
// lowest-index tie-break (JAX lax.top_k semantics).
__device__ __forceinline__ unsigned scanExcl256(unsigned v, unsigned* wsum, unsigned* total) {
    int t = threadIdx.x;
    __syncthreads();             // protect wsum/total reuse across calls
    unsigned x = v;
#pragma unroll
    for (int o = 1; o < 32; o <<= 1) {
        unsigned y = __shfl_up_sync(0xffffffffu, x, o);
        if ((t & 31) >= o) x += y;
    }
    if ((t & 31) == 31) wsum[t >> 5] = x;
    __syncthreads();
    if (t == 0) {
        unsigned acc = 0;
#pragma unroll
        for (int w = 0; w < 8; w++) { unsigned s = wsum[w]; wsum[w] = acc; acc += s; }
        *total = acc;
    }
    __syncthreads();
    return x - v + wsum[t >> 5];
}

__global__ __launch_bounds__(256) void k_select() {
    int row = blockIdx.x;              // 0 .. BB*NN-1
    const float* drow = g_D + (size_t)row * NN;
    __shared__ unsigned keys[NN];      // 8 KB
    __shared__ unsigned hist[4096];    // 16 KB
    __shared__ unsigned wsum[8];
    __shared__ unsigned stotal;
    __shared__ unsigned s_b, s_r;

    int t = threadIdx.x;
    // load row, map float -> order-preserving uint
    for (int i = t; i < NN; i += 256) {
        unsigned b = __float_as_uint(drow[i]);
        keys[i] = (b & 0x80000000u) ? ~b : (b | 0x80000000u);
    }
    for (int i = t; i < 4096; i += 256) hist[i] = 0;
    __syncthreads();
    for (int i = t; i < NN; i += 256) atomicAdd(&hist[keys[i] >> 20], 1u);
    __syncthreads();

    const unsigned RK = KNN - 1;   // 0-based rank of the k-th smallest

    // ---- level 1: top 12 bits
    unsigned seg = 0;
#pragma unroll
    for (int j = 0; j < 16; j++) seg += hist[t * 16 + j];
    unsigned off = scanExcl256(seg, wsum, &stotal);
    if (seg && off <= RK && RK < off + seg) {
        unsigned cum = off;
        for (int j = 0; j < 16; j++) {
            unsigned h = hist[t * 16 + j];
            if (cum + h > RK) { s_b = t * 16 + j; s_r = RK - cum; break; }
            cum += h;
        }
    }
    __syncthreads();
    unsigned b1 = s_b, r2 = s_r;

    // ---- level 2: middle 12 bits among keys with top12 == b1
    for (int i = t; i < 4096; i += 256) hist[i] = 0;
    __syncthreads();
    for (int i = t; i < NN; i += 256) {
        unsigned k = keys[i];
        if ((k >> 20) == b1) atomicAdd(&hist[(k >> 8) & 0xFFFu], 1u);
    }
    __syncthreads();
    seg = 0;
#pragma unroll
    for (int j = 0; j < 16; j++) seg += hist[t * 16 + j];
    off = scanExcl256(seg, wsum, &stotal);
    if (seg && off <= r2 && r2 < off + seg) {
        unsigned cum = off;
        for (int j = 0; j < 16; j++) {
            unsigned h = hist[t * 16 + j];
            if (cum + h > r2) { s_b = t * 16 + j; s_r = r2 - cum; break; }
            cum += h;
        }
    }
    __syncthreads();
    unsigned b2 = s_b, r3 = s_r;
    unsigned pfx = (b1 << 12) | b2;    // top 24 bits

    // ---- level 3: low 8 bits among keys with top24 == pfx
    hist[t] = 0;
    __syncthreads();
    for (int i = t; i < NN; i += 256) {
        unsigned k = keys[i];
        if ((k >> 8) == pfx) atomicAdd(&hist[k & 0xFFu], 1u);
    }
    __syncthreads();
    seg = hist[t];
    off = scanExcl256(seg, wsum, &stotal);
    if (seg && off <= r3 && r3 < off + seg) s_b = t;
    __syncthreads();
    unsigned T = (pfx << 8) | s_b;     // exact key of the 20th smallest

    // ---- output: indices with key < T, then key == T by increasing index
    unsigned myk[8];
    unsigned clt = 0, ceq = 0;
#pragma unroll
    for (int j = 0; j < 8; j++) {
        myk[j] = keys[t * 8 + j];
        clt += (myk[j] < T) ? 1u : 0u;
        ceq += (myk[j] == T) ? 1u : 0u;
    }
    unsigned packed = (clt << 16) | ceq;
    unsigned poff = scanExcl256(packed, wsum, &stotal);
    unsigned totLt = stotal >> 16;
    unsigned lp = poff >> 16;
    unsigned ep = poff & 0xFFFFu;
    int* out = g_idx + (size_t)row * KNN;
#pragma unroll
    for (int j = 0; j < 8; j++) {
        unsigned k = myk[j];
        if (k < T) {
            out[lp++] = t * 8 + j;
        } else if (k == T) {
            unsigned pos = totLt + ep;
            if (pos < KNN) out[pos] = t * 8 + j;
            ep++;
        }
    }
}

// gather 20 neighbor rows of U, reduce max / sum / sumsq over k
__global__ void k_edge_reduce(int outOff, int O) {
    int n = blockIdx.x, b = blockIdx.y;
    __shared__ int sidx[KNN];
    size_t row = (size_t)b * NN + n;
    if (threadIdx.x < KNN) sidx[threadIdx.x] = g_idx[row * KNN + threadIdx.x];
    __syncthreads();
    const float* Ub = g_U + (size_t)b * NN * O;
    const float* Vb = g_V + row * O;
    for (int o = threadIdx.x; o < O; o += blockDim.x) {
        float v = Vb[o];
        float mx = -INFINITY, s = 0.f, ss = 0.f;
#pragma unroll
        for (int j = 0; j < KNN; j++) {
            float u = Ub[(size_t)sidx[j] * O + o] + v;
            mx = fmaxf(mx, u);
            s += u; ss += u * u;
        }
        g_F[row * CSTR + outOff + o] = mx;   // raw max; BN+lrelu applied later
        g_pS[row * O + o]  = s;
        g_pSS[row * O + o] = ss;
    }
}

// deterministic two-stage column reductions
__global__ void k_chunk_reduce(int O) {
    int o = blockIdx.x * blockDim.x + threadIdx.x;
    int ch = blockIdx.y;
    if (o >= O) return;
    int r0 = ch * ROWS_PER_CHUNK;
    float s = 0.f, ss = 0.f;
    for (int r = r0; r < r0 + ROWS_PER_CHUNK; r++) {
        s  += g_pS[(size_t)r * O + o];
        ss += g_pSS[(size_t)r * O + o];
    }
    g_cS[ch * O + o] = s;
    g_cSS[ch * O + o] = ss;
}

__global__ void k_edge_stats(const float* __restrict__ g, const float* __restrict__ bet, int O) {
    int o = blockIdx.x * blockDim.x + threadIdx.x;
    if (o >= O) return;
    double s = 0.0, ss = 0.0;
    for (int ch = 0; ch < NCHUNK; ch++) { s += (double)g_cS[ch * O + o]; ss += (double)g_cSS[ch * O + o]; }
    double cnt = (double)BB * NN * KNN;
    double m = s / cnt;
    double var = ss / cnt - m * m;
    float sc = g[o] * rsqrtf((float)var + EPSV);
    g_scale[o] = sc;
    g_bias[o]  = bet[o] - (float)m * sc;
}

__global__ void k_bn_lrelu(int outOff, int O, int total) {
    int i = blockIdx.x * blockDim.x + threadIdx.x;
    if (i >= total) return;
    int o = i % O;
    size_t row = (size_t)(i / O);
    size_t p = row * CSTR + outOff + o;
    float v = g_F[p] * g_scale[o] + g_bias[o];
    g_F[p] = v > 0.f ? v : 0.2f * v;
}

// h stats: per-column sum/sumsq (over b,n) and per-(b,col) max
__global__ void k_ht_chunk() {
    int o = blockIdx.x * blockDim.x + threadIdx.x;
    int ch = blockIdx.y;
    if (o >= 2048) return;
    int r0 = ch * ROWS_PER_CHUNK;
    float s = 0.f, ss = 0.f, mx = -INFINITY;
    for (int r = r0; r < r0 + ROWS_PER_CHUNK; r++) {
        float v = g_HT[(size_t)r * 2048 + o];
        s += v; ss += v * v; mx = fmaxf(mx, v);
    }
    g_cS[ch * 2048 + o] = s;
    g_cSS[ch * 2048 + o] = ss;
    g_cMax[ch * 2048 + o] = mx;
}

__global__ void k_ht_final(const float* __restrict__ g5, const float* __restrict__ b5) {
    int o = blockIdx.x * blockDim.x + threadIdx.x;
    if (o >= 2048) return;
    double s = 0.0, ss = 0.0;
    float mb[BB];
#pragma unroll
    for (int b = 0; b < BB; b++) mb[b] = -INFINITY;
    for (int ch = 0; ch < NCHUNK; ch++) {
        s  += (double)g_cS[ch * 2048 + o];
        ss += (double)g_cSS[ch * 2048 + o];
        float m = g_cMax[ch * 2048 + o];
        int b = ch >> 3;   // 8 chunks of 256 rows per batch
        mb[b] = fmaxf(mb[b], m);
    }
    double cnt = (double)(BB * NN);
    double md = s / cnt;
    float var = (float)(ss / cnt - md * md);
    float sc = g5[o] * rsqrtf(var + EPSV);
    float bs = b5[o] - (float)md * sc;
#pragma unroll
    for (int b = 0; b < BB; b++) {
        float v = mb[b] * sc + bs;
        g_p[b * 2048 + o] = v > 0.f ? v : 0.2f * v;
    }
}

// FC + bias + BN(over batch of 4) + relu.  inB!=null => input is concat [inA(CA) ; inB(CB)]
__global__ void k_fc_bn(const float* __restrict__ W, const float* __restrict__ wb,
                        const float* __restrict__ inA, int CA,
                        const float* __restrict__ inB, int CB,
                        const float* __restrict__ g, const float* __restrict__ bet,
                        float* __restrict__ out, int O)
{
    int o = blockIdx.x;
    int Cin = CA + CB;
    const float* w = W + (size_t)o * Cin;
    float a0 = 0.f, a1 = 0.f, a2 = 0.f, a3 = 0.f;
    for (int c = threadIdx.x; c < Cin; c += blockDim.x) {
        float wv = w[c];
        float x0, x1, x2, x3;
        if (c < CA) {
            x0 = inA[c]; x1 = inA[CA + c]; x2 = inA[2 * CA + c]; x3 = inA[3 * CA + c];
        } else {
            int cc = c - CA;
            x0 = inB[cc]; x1 = inB[CB + cc]; x2 = inB[2 * CB + cc]; x3 = inB[3 * CB + cc];
        }
        a0 += wv * x0; a1 += wv * x1; a2 += wv * x2; a3 += wv * x3;
    }
    __shared__ float sm[4][256];
    sm[0][threadIdx.x] = a0; sm[1][threadIdx.x] = a1;
    sm[2][threadIdx.x] = a2; sm[3][threadIdx.x] = a3;
    __syncthreads();
    for (int st = 128; st > 0; st >>= 1) {
        if (threadIdx.x < st) {
#pragma unroll
            for (int b = 0; b < 4; b++) sm[b][threadIdx.x] += sm[b][threadIdx.x + st];
        }
        __syncthreads();
    }
    if (threadIdx.x == 0) {
        float y[4];
#pragma unroll
        for (int b = 0; b < 4; b++) y[b] = sm[b][0] + wb[o];
        float m = (y[0] + y[1] + y[2] + y[3]) * 0.25f;
        float var = 0.f;
#pragma unroll
        for (int b = 0; b < 4; b++) { float d = y[b] - m; var += d * d; }
        var *= 0.25f;
        float sc = g[o] * rsqrtf(var + EPSV);
#pragma unroll
        for (int b = 0; b < 4; b++) {
            float z = (y[b] - m) * sc + bet[o];
            out[b * O + o] = z > 0.f ? z : 0.f;
        }
    }
}

__global__ void k_fc_out(const float* __restrict__ W, const float* __restrict__ wb,
                         float* __restrict__ out)
{
    int o = blockIdx.x;  // 0..399
    const float* w = W + (size_t)o * 4096;
    float a0 = 0.f, a1 = 0.f, a2 = 0.f, a3 = 0.f;
    for (int c = threadIdx.x; c < 4096; c += blockDim.x) {
        float wv = w[c];
        a0 += wv * g_z7[c];
        a1 += wv * g_z7[4096 + c];
        a2 += wv * g_z7[2 * 4096 + c];
        a3 += wv * g_z7[3 * 4096 + c];
    }
    __shared__ float sm[4][256];
    sm[0][threadIdx.x] = a0; sm[1][threadIdx.x] = a1;
    sm[2][threadIdx.x] = a2; sm[3][threadIdx.x] = a3;
    __syncthreads();
    for (int st = 128; st > 0; st >>= 1) {
        if (threadIdx.x < st) {
#pragma unroll
            for (int b = 0; b < 4; b++) sm[b][threadIdx.x] += sm[b][threadIdx.x + st];
        }
        __syncthreads();
    }
    if (threadIdx.x == 0) {
#pragma unroll
        for (int b = 0; b < 4; b++) {
            out[b * 400 + o] = tanhf(sm[b][0] + wb[o]);
        }
    }
}

// ---------------- launch ----------------
extern "C" void kernel_launch(void* const* d_in, const int* in_sizes, int n_in,
                              void* d_out, int out_size) {
    (void)in_sizes; (void)n_in; (void)out_size;
    const float* x   = (const float*)d_in[0];
    const float* w1  = (const float*)d_in[1];
    const float* g1  = (const float*)d_in[2];
    const float* b1  = (const float*)d_in[3];
    const float* w2  = (const float*)d_in[4];
    const float* g2  = (const float*)d_in[5];
    const float* b2  = (const float*)d_in[6];
    const float* w3  = (const float*)d_in[7];
    const float* g3  = (const float*)d_in[8];
    const float* b3  = (const float*)d_in[9];
    const float* w4  = (const float*)d_in[10];
    const float* g4  = (const float*)d_in[11];
    const float* b4  = (const float*)d_in[12];
    const float* w5  = (const float*)d_in[13];
    const float* g5  = (const float*)d_in[14];
    const float* b5  = (const float*)d_in[15];
    const float* w6  = (const float*)d_in[16];
    const float* wb6 = (const float*)d_in[17];
    const float* g6  = (const float*)d_in[18];
    const float* b6  = (const float*)d_in[19];
    const float* w7  = (const float*)d_in[20];
    const float* wb7 = (const float*)d_in[21];
    const float* g7  = (const float*)d_in[22];
    const float* b7  = (const float*)d_in[23];
    const float* w8  = (const float*)d_in[24];
    const float* wb8 = (const float*)d_in[25];
    float* out = (float*)d_out;

    float *pF, *pD, *pU, *pV, *pHT, *px2, *pWd, *pp, *pz6, *pz7;
    cudaGetSymbolAddress((void**)&pF,  g_F);
    cudaGetSymbolAddress((void**)&pD,  g_D);
    cudaGetSymbolAddress((void**)&pU,  g_U);
    cudaGetSymbolAddress((void**)&pV,  g_V);
    cudaGetSymbolAddress((void**)&pHT, g_HT);
    cudaGetSymbolAddress((void**)&px2, g_x2);
    cudaGetSymbolAddress((void**)&pWd, g_Wd);
    cudaGetSymbolAddress((void**)&pp,  g_p);
    cudaGetSymbolAddress((void**)&pz6, g_z6);
    cudaGetSymbolAddress((void**)&pz7, g_z7);

    dim3 thrS(16, 16);

    k_transpose_in<<<(BB * NN + 255) / 256, 256>>>(x);

    struct Layer { int inOff, C, outOff, O; const float *w, *g, *bet; };
    Layer L[4] = {
        {0,   3,   3,   64,  w1, g1, b1},
        {3,   64,  67,  128, w2, g2, b2},
        {67,  128, 195, 256, w3, g3, b3},
        {195, 256, 451, 512, w4, g4, b4},
    };

    for (int l = 0; l < 4; l++) {
        int inOff = L[l].inOff, C = L[l].C, outOff = L[l].outOff, O = L[l].O;
        const float* w = L[l].w;

        k_sqnorm<<<(BB * NN + 255) / 256, 256>>>(inOff, C);

        // pairwise distances (DISCRETE path — unchanged bit-exact kernel)
        sgemm_nt<<<dim3(NN / 64, NN / 64, BB), thrS>>>(
            pF + inOff, CSTR, (size_t)NN * CSTR,
            pF + inOff, CSTR, (size_t)NN * CSTR,
            pD, NN, (size_t)NN * NN,
            NN, NN, C, px2, 1);

        // exact top-20 selection (radix, lowest-index tie-break)
        k_select<<<BB * NN, 256>>>();

        k_wdiff<<<(O * C + 255) / 256, 256>>>(w, C, O);

        if (O >= 128) {
            // U = X @ Wa^T  (continuous path -> fast f32x2 GEMM)
            sgemm_nt_128<<<dim3(O / 128, NN / 128, BB), 256>>>(
                pF + inOff, CSTR, (size_t)NN * CSTR,
                w, 2 * C, 0,
                pU, O, (size_t)NN * O,
                NN, O, C);
            // V = X @ (Wb-Wa)^T
            sgemm_nt_128<<<dim3(O / 128, NN / 128, BB), 256>>>(
                pF + inOff, CSTR, (size_t)NN * CSTR,
                pWd, C, 0,
                pV, O, (size_t)NN * O,
                NN, O, C);
        } else {
            sgemm_nt<<<dim3((O + 63) / 64, NN / 64, BB), thrS>>>(
                pF + inOff, CSTR, (size_t)NN * CSTR,
                w, 2 * C, 0,
                pU, O, (size_t)NN * O,
                NN, O, C, (const float*)0, 0);
            sgemm_nt<<<dim3((O + 63) / 64, NN / 64, BB), thrS>>>(
                pF + inOff, CSTR, (size_t)NN * CSTR,
                pWd, C, 0,
                pV, O, (size_t)NN * O,
                NN, O, C, (const float*)0, 0);
        }

        int ethreads = (O < 256) ? O : 256;
        k_edge_reduce<<<dim3(NN, BB), ethreads>>>(outOff, O);
        k_chunk_reduce<<<dim3((O + 255) / 256, NCHUNK), 256>>>(O);
        k_edge_stats<<<(O + 255) / 256, 256>>>(L[l].g, L[l].bet, O);
        int total = BB * NN * O;
        k_bn_lrelu<<<(total + 255) / 256, 256>>>(outOff, O, total);
    }

    // h^T[b][n][o] = F[b][n][:] . w5[o][:]   (continuous path -> fast GEMM)
    sgemm_nt_128<<<dim3(2048 / 128, NN / 128, BB), 256>>>(
        pF, CSTR, (size_t)NN * CSTR,
        w5, CSTR, 0,
        pHT, 2048, (size_t)NN * 2048,
        NN, 2048, CSTR);

    k_ht_chunk<<<dim3(8, NCHUNK), 256>>>();
    k_ht_final<<<8, 256>>>(g5, b5);

    k_fc_bn<<<2048, 256>>>(w6, wb6, pp, 2048, (const float*)0, 0, g6, b6, pz6, 2048);
    k_fc_bn<<<4096, 256>>>(w7, wb7, pz6, 2048, pp, 2048, g7, b7, pz7, 4096);
    k_fc_out<<<400, 256>>>(w8, wb8, out);
}

// round 8
// speedup vs baseline: 1.8265x; 1.0625x over previous
#include <cuda_runtime.h>
#include <math.h>

#define BB 4
#define NN 2048
#define KNN 20
#define CSTR 963
#define EPSV 1e-5f
#define NCHUNK 32
#define ROWS_PER_CHUNK ((BB*NN)/NCHUNK)   // 256

// ---------------- scratch (device globals; no allocation allowed) ----------------
__device__ float g_F[(size_t)BB*NN*CSTR];      // concat features, layout [b][n][c]
__device__ float g_D[(size_t)BB*NN*NN];        // pairwise distances per batch
__device__ int   g_idx[(size_t)BB*NN*KNN];     // knn indices
__device__ float g_U[(size_t)BB*NN*512];       // U[b][m][o]
__device__ float g_V[(size_t)BB*NN*512];       // V[b][n][o]
__device__ float g_pS[(size_t)BB*NN*512];      // per-(b,n) partial sums over k
__device__ float g_pSS[(size_t)BB*NN*512];     // per-(b,n) partial sumsq over k
__device__ float g_cS[NCHUNK*2048];
__device__ float g_cSS[NCHUNK*2048];
__device__ float g_cMax[NCHUNK*2048];
__device__ float g_x2[BB*NN];
__device__ float g_scale[2048];
__device__ float g_bias[2048];
__device__ float g_Wd[512*256];
__device__ float g_HT[(size_t)BB*NN*2048];     // h transposed: [b][n][o]
__device__ float g_p[BB*2048];
__device__ float g_z6[BB*2048];
__device__ float g_z7[BB*4096];

// ---------------- f32x2 helpers (Blackwell packed fp32 FMA) ----------------
__device__ __forceinline__ unsigned long long dup2(float a) {
    unsigned long long r;
    asm("mov.b64 %0, {%1, %1};" : "=l"(r) : "f"(a));
    return r;
}
__device__ __forceinline__ unsigned long long fma2(unsigned long long a,
                                                   unsigned long long b,
                                                   unsigned long long c) {
    unsigned long long d;
    asm("fma.rn.f32x2 %0, %1, %2, %3;" : "=l"(d) : "l"(a), "l"(b), "l"(c));
    return d;
}

// ---------------- big NT SGEMM: 128x128 tile, 8x8/thread, f32x2, double buffer --------
// C[i,j] = sum_k A[i,k]*B[j,k]
__global__ __launch_bounds__(256) void sgemm_nt_128(
        const float* __restrict__ A, int lda, size_t sA,
        const float* __restrict__ B, int ldb, size_t sB,
        float* __restrict__ C, int ldc, size_t sC,
        int M, int N, int K)
{
    __shared__ float As[2][16][128];
    __shared__ float Bs[2][16][128];

    int bz = blockIdx.z;
    A += (size_t)bz * sA;
    B += (size_t)bz * sB;
    C += (size_t)bz * sC;

    int tid = threadIdx.x;
    int tx = tid & 15, ty = tid >> 4;
    int row0 = blockIdx.y * 128;
    int col0 = blockIdx.x * 128;

    unsigned long long acc[8][4];
#pragma unroll
    for (int i = 0; i < 8; i++)
#pragma unroll
        for (int j = 0; j < 4; j++) acc[i][j] = 0ULL;

    int ntiles = (K + 15) >> 4;
    float ra[8], rb[8];

#pragma unroll
    for (int e = 0; e < 8; e++) {
        int idx = tid + e * 256;
        int r = idx >> 4, kk = idx & 15;
        ra[e] = (row0 + r < M && kk < K) ? A[(size_t)(row0 + r) * lda + kk] : 0.f;
        rb[e] = (col0 + r < N && kk < K) ? B[(size_t)(col0 + r) * ldb + kk] : 0.f;
    }
#pragma unroll
    for (int e = 0; e < 8; e++) {
        int idx = tid + e * 256;
        int r = idx >> 4, kk = idx & 15;
        As[0][kk][r] = ra[e];
        Bs[0][kk][r] = rb[e];
    }
    __syncthreads();

    int buf = 0;
    for (int t = 0; t < ntiles; t++) {
        int k0n = (t + 1) * 16;
        if (t + 1 < ntiles) {
#pragma unroll
            for (int e = 0; e < 8; e++) {
                int idx = tid + e * 256;
                int r = idx >> 4, kk = idx & 15;
                int gk = k0n + kk;
                ra[e] = (row0 + r < M && gk < K) ? A[(size_t)(row0 + r) * lda + gk] : 0.f;
                rb[e] = (col0 + r < N && gk < K) ? B[(size_t)(col0 + r) * ldb + gk] : 0.f;
            }
        }

#pragma unroll
        for (int kk = 0; kk < 16; kk++) {
            float4 a0 = *(const float4*)&As[buf][kk][ty * 8];
            float4 a1 = *(const float4*)&As[buf][kk][ty * 8 + 4];
            ulonglong2 bv0 = *(const ulonglong2*)&Bs[buf][kk][tx * 8];
            ulonglong2 bv1 = *(const ulonglong2*)&Bs[buf][kk][tx * 8 + 4];
            unsigned long long bp[4] = {bv0.x, bv0.y, bv1.x, bv1.y};
            float av[8] = {a0.x, a0.y, a0.z, a0.w, a1.x, a1.y, a1.z, a1.w};
#pragma unroll
            for (int i = 0; i < 8; i++) {
                unsigned long long ad = dup2(av[i]);
#pragma unroll
                for (int j = 0; j < 4; j++)
                    acc[i][j] = fma2(ad, bp[j], acc[i][j]);
            }
        }

        if (t + 1 < ntiles) {
#pragma unroll
            for (int e = 0; e < 8; e++) {
                int idx = tid + e * 256;
                int r = idx >> 4, kk = idx & 15;
                As[buf ^ 1][kk][r] = ra[e];
                Bs[buf ^ 1][kk][r] = rb[e];
            }
        }
        __syncthreads();
        buf ^= 1;
    }

#pragma unroll
    for (int i = 0; i < 8; i++) {
        int r = row0 + ty * 8 + i;
        if (r >= M) continue;
#pragma unroll
        for (int j = 0; j < 4; j++) {
            int c = col0 + tx * 8 + j * 2;
            float2 v = *(float2*)&acc[i][j];
            if (c + 1 < N) {
                *(float2*)&C[(size_t)r * ldc + c] = v;
            } else if (c < N) {
                C[(size_t)r * ldc + c] = v.x;
            }
        }
    }
}

// ---------------- distance GEMM: same 128x128 f32x2 core + dist epilogue --------------
// D[i,j] = sq[i] + sq[j] - 2 * sum_k A[i,k]*A[j,k]   (square M=N=NN, no bounds tails)
__global__ __launch_bounds__(256) void sgemm_dist_128(
        const float* __restrict__ A, int lda, size_t sA,
        float* __restrict__ C, int ldc, size_t sC,
        int K, const float* __restrict__ sq)
{
    __shared__ float As[2][16][128];
    __shared__ float Bs[2][16][128];

    int bz = blockIdx.z;
    A += (size_t)bz * sA;
    C += (size_t)bz * sC;
    const float* sqb = sq + (size_t)bz * NN;

    int tid = threadIdx.x;
    int tx = tid & 15, ty = tid >> 4;
    int row0 = blockIdx.y * 128;
    int col0 = blockIdx.x * 128;

    unsigned long long acc[8][4];
#pragma unroll
    for (int i = 0; i < 8; i++)
#pragma unroll
        for (int j = 0; j < 4; j++) acc[i][j] = 0ULL;

    int ntiles = (K + 15) >> 4;
    float ra[8], rb[8];

#pragma unroll
    for (int e = 0; e < 8; e++) {
        int idx = tid + e * 256;
        int r = idx >> 4, kk = idx & 15;
        ra[e] = (kk < K) ? A[(size_t)(row0 + r) * lda + kk] : 0.f;
        rb[e] = (kk < K) ? A[(size_t)(col0 + r) * lda + kk] : 0.f;
    }
#pragma unroll
    for (int e = 0; e < 8; e++) {
        int idx = tid + e * 256;
        int r = idx >> 4, kk = idx & 15;
        As[0][kk][r] = ra[e];
        Bs[0][kk][r] = rb[e];
    }
    __syncthreads();

    int buf = 0;
    for (int t = 0; t < ntiles; t++) {
        int k0n = (t + 1) * 16;
        if (t + 1 < ntiles) {
#pragma unroll
            for (int e = 0; e < 8; e++) {
                int idx = tid + e * 256;
                int r = idx >> 4, kk = idx & 15;
                int gk = k0n + kk;
                ra[e] = (gk < K) ? A[(size_t)(row0 + r) * lda + gk] : 0.f;
                rb[e] = (gk < K) ? A[(size_t)(col0 + r) * lda + gk] : 0.f;
            }
        }

#pragma unroll
        for (int kk = 0; kk < 16; kk++) {
            float4 a0 = *(const float4*)&As[buf][kk][ty * 8];
            float4 a1 = *(const float4*)&As[buf][kk][ty * 8 + 4];
            ulonglong2 bv0 = *(const ulonglong2*)&Bs[buf][kk][tx * 8];
            ulonglong2 bv1 = *(const ulonglong2*)&Bs[buf][kk][tx * 8 + 4];
            unsigned long long bp[4] = {bv0.x, bv0.y, bv1.x, bv1.y};
            float av[8] = {a0.x, a0.y, a0.z, a0.w, a1.x, a1.y, a1.z, a1.w};
#pragma unroll
            for (int i = 0; i < 8; i++) {
                unsigned long long ad = dup2(av[i]);
#pragma unroll
                for (int j = 0; j < 4; j++)
                    acc[i][j] = fma2(ad, bp[j], acc[i][j]);
            }
        }

        if (t + 1 < ntiles) {
#pragma unroll
            for (int e = 0; e < 8; e++) {
                int idx = tid + e * 256;
                int r = idx >> 4, kk = idx & 15;
                As[buf ^ 1][kk][r] = ra[e];
                Bs[buf ^ 1][kk][r] = rb[e];
            }
        }
        __syncthreads();
        buf ^= 1;
    }

#pragma unroll
    for (int i = 0; i < 8; i++) {
        int r = row0 + ty * 8 + i;
        float sr = sqb[r];
#pragma unroll
        for (int j = 0; j < 4; j++) {
            int c = col0 + tx * 8 + j * 2;
            float2 v = *(float2*)&acc[i][j];
            v.x = sr + sqb[c] - 2.f * v.x;
            v.y = sr + sqb[c + 1] - 2.f * v.y;
            *(float2*)&C[(size_t)r * ldc + c] = v;
        }
    }
}

// ---------------- small NT SGEMM (layer-1 U/V: O=64) ----------------
__global__ void sgemm_nt(const float* __restrict__ A, int lda, size_t sA,
                         const float* __restrict__ B, int ldb, size_t sB,
                         float* __restrict__ C, int ldc, size_t sC,
                         int M, int N, int K)
{
    __shared__ float As[16][64];
    __shared__ float Bs[16][64];
    int bz = blockIdx.z;
    A += (size_t)bz * sA;
    B += (size_t)bz * sB;
    C += (size_t)bz * sC;

    int tid = threadIdx.y * 16 + threadIdx.x;
    int row0 = blockIdx.y * 64;
    int col0 = blockIdx.x * 64;

    float acc[4][4];
#pragma unroll
    for (int i = 0; i < 4; i++)
#pragma unroll
        for (int j = 0; j < 4; j++) acc[i][j] = 0.f;

    for (int k0 = 0; k0 < K; k0 += 16) {
#pragma unroll
        for (int e = 0; e < 4; e++) {
            int idx = tid + e * 256;
            int r  = idx >> 4;
            int kk = idx & 15;
            int gk = k0 + kk;
            int gr = row0 + r;
            As[kk][r] = (gr < M && gk < K) ? A[(size_t)gr * lda + gk] : 0.f;
            int gc = col0 + r;
            Bs[kk][r] = (gc < N && gk < K) ? B[(size_t)gc * ldb + gk] : 0.f;
        }
        __syncthreads();
#pragma unroll
        for (int kk = 0; kk < 16; kk++) {
            float4 av = *(const float4*)&As[kk][threadIdx.y * 4];
            float4 bv = *(const float4*)&Bs[kk][threadIdx.x * 4];
            float a[4] = {av.x, av.y, av.z, av.w};
            float bb[4] = {bv.x, bv.y, bv.z, bv.w};
#pragma unroll
            for (int i = 0; i < 4; i++)
#pragma unroll
                for (int j = 0; j < 4; j++)
                    acc[i][j] += a[i] * bb[j];
        }
        __syncthreads();
    }

#pragma unroll
    for (int i = 0; i < 4; i++) {
        int r = row0 + threadIdx.y * 4 + i;
        if (r >= M) continue;
#pragma unroll
        for (int j = 0; j < 4; j++) {
            int c = col0 + threadIdx.x * 4 + j;
            if (c >= N) continue;
            C[(size_t)r * ldc + c] = acc[i][j];
        }
    }
}

// ---------------- helpers ----------------
__global__ void k_transpose_in(const float* __restrict__ x) {
    int i = blockIdx.x * blockDim.x + threadIdx.x;
    if (i >= BB * NN) return;
    int b = i / NN, n = i % NN;
    float* dst = g_F + (size_t)i * CSTR;
    dst[0] = x[(size_t)b * 3 * NN + 0 * NN + n];
    dst[1] = x[(size_t)b * 3 * NN + 1 * NN + n];
    dst[2] = x[(size_t)b * 3 * NN + 2 * NN + n];
}

__global__ void k_sqnorm(int off, int C) {
    int i = blockIdx.x * blockDim.x + threadIdx.x;
    if (i >= BB * NN) return;
    const float* row = g_F + (size_t)i * CSTR + off;
    float s = 0.f;
    for (int c = 0; c < C; c++) { float v = row[c]; s += v * v; }
    g_x2[i] = s;
}

__global__ void k_wdiff(const float* __restrict__ w, int C, int O) {
    int i = blockIdx.x * blockDim.x + threadIdx.x;
    if (i >= O * C) return;
    int o = i / C, c = i % C;
    g_Wd[i] = w[(size_t)o * 2 * C + C + c] - w[(size_t)o * 2 * C + c];
}

// ---------------- exact kNN selection via 3-level radix histogram ----------------
__device__ __forceinline__ unsigned scanExcl256(unsigned v, unsigned* wsum, unsigned* total) {
    int t = threadIdx.x;
    __syncthreads();
    unsigned x = v;
#pragma unroll
    for (int o = 1; o < 32; o <<= 1) {
        unsigned y = __shfl_up_sync(0xffffffffu, x, o);
        if ((t & 31) >= o) x += y;
    }
    if ((t & 31) == 31) wsum[t >> 5] = x;
    __syncthreads();
    if (t == 0) {
        unsigned acc = 0;
#pragma unroll
        for (int w = 0; w < 8; w++) { unsigned s = wsum[w]; wsum[w] = acc; acc += s; }
        *total = acc;
    }
    __syncthreads();
    return x - v + wsum[t >> 5];
}

__global__ __launch_bounds__(256) void k_select() {
    int row = blockIdx.x;
    const float* drow = g_D + (size_t)row * NN;
    __shared__ unsigned keys[NN];
    __shared__ unsigned hist[4096];
    __shared__ unsigned wsum[8];
    __shared__ unsigned stotal;
    __shared__ unsigned s_b, s_r;

    int t = threadIdx.x;
    for (int i = t; i < NN; i += 256) {
        unsigned b = __float_as_uint(drow[i]);
        keys[i] = (b & 0x80000000u) ? ~b : (b | 0x80000000u);
    }
    for (int i = t; i < 4096; i += 256) hist[i] = 0;
    __syncthreads();
    for (int i = t; i < NN; i += 256) atomicAdd(&hist[keys[i] >> 20], 1u);
    __syncthreads();

    const unsigned RK = KNN - 1;

    unsigned seg = 0;
#pragma unroll
    for (int j = 0; j < 16; j++) seg += hist[t * 16 + j];
    unsigned off = scanExcl256(seg, wsum, &stotal);
    if (seg && off <= RK && RK < off + seg) {
        unsigned cum = off;
        for (int j = 0; j < 16; j++) {
            unsigned h = hist[t * 16 + j];
            if (cum + h > RK) { s_b = t * 16 + j; s_r = RK - cum; break; }
            cum += h;
        }
    }
    __syncthreads();
    unsigned b1 = s_b, r2 = s_r;

    for (int i = t; i < 4096; i += 256) hist[i] = 0;
    __syncthreads();
    for (int i = t; i < NN; i += 256) {
        unsigned k = keys[i];
        if ((k >> 20) == b1) atomicAdd(&hist[(k >> 8) & 0xFFFu], 1u);
    }
    __syncthreads();
    seg = 0;
#pragma unroll
    for (int j = 0; j < 16; j++) seg += hist[t * 16 + j];
    off = scanExcl256(seg, wsum, &stotal);
    if (seg && off <= r2 && r2 < off + seg) {
        unsigned cum = off;
        for (int j = 0; j < 16; j++) {
            unsigned h = hist[t * 16 + j];
            if (cum + h > r2) { s_b = t * 16 + j; s_r = r2 - cum; break; }
            cum += h;
        }
    }
    __syncthreads();
    unsigned b2 = s_b, r3 = s_r;
    unsigned pfx = (b1 << 12) | b2;

    hist[t] = 0;
    __syncthreads();
    for (int i = t; i < NN; i += 256) {
        unsigned k = keys[i];
        if ((k >> 8) == pfx) atomicAdd(&hist[k & 0xFFu], 1u);
    }
    __syncthreads();
    seg = hist[t];
    off = scanExcl256(seg, wsum, &stotal);
    if (seg && off <= r3 && r3 < off + seg) s_b = t;
    __syncthreads();
    unsigned T = (pfx << 8) | s_b;

    unsigned myk[8];
    unsigned clt = 0, ceq = 0;
#pragma unroll
    for (int j = 0; j < 8; j++) {
        myk[j] = keys[t * 8 + j];
        clt += (myk[j] < T) ? 1u : 0u;
        ceq += (myk[j] == T) ? 1u : 0u;
    }
    unsigned packed = (clt << 16) | ceq;
    unsigned poff = scanExcl256(packed, wsum, &stotal);
    unsigned totLt = stotal >> 16;
    unsigned lp = poff >> 16;
    unsigned ep = poff & 0xFFFFu;
    int* out = g_idx + (size_t)row * KNN;
#pragma unroll
    for (int j = 0; j < 8; j++) {
        unsigned k = myk[j];
        if (k < T) {
            out[lp++] = t * 8 + j;
        } else if (k == T) {
            unsigned pos = totLt + ep;
            if (pos < KNN) out[pos] = t * 8 + j;
            ep++;
        }
    }
}

// gather 20 neighbor rows of U, reduce max / sum / sumsq over k
__global__ void k_edge_reduce(int outOff, int O) {
    int n = blockIdx.x, b = blockIdx.y;
    __shared__ int sidx[KNN];
    size_t row = (size_t)b * NN + n;
    if (threadIdx.x < KNN) sidx[threadIdx.x] = g_idx[row * KNN + threadIdx.x];
    __syncthreads();
    const float* Ub = g_U + (size_t)b * NN * O;
    const float* Vb = g_V + row * O;
    for (int o = threadIdx.x; o < O; o += blockDim.x) {
        float v = Vb[o];
        float mx = -INFINITY, s = 0.f, ss = 0.f;
#pragma unroll
        for (int j = 0; j < KNN; j++) {
            float u = Ub[(size_t)sidx[j] * O + o] + v;
            mx = fmaxf(mx, u);
            s += u; ss += u * u;
        }
        g_F[row * CSTR + outOff + o] = mx;
        g_pS[row * O + o]  = s;
        g_pSS[row * O + o] = ss;
    }
}

// deterministic two-stage column reductions
__global__ void k_chunk_reduce(int O) {
    int o = blockIdx.x * blockDim.x + threadIdx.x;
    int ch = blockIdx.y;
    if (o >= O) return;
    int r0 = ch * ROWS_PER_CHUNK;
    float s = 0.f, ss = 0.f;
    for (int r = r0; r < r0 + ROWS_PER_CHUNK; r++) {
        s  += g_pS[(size_t)r * O + o];
        ss += g_pSS[(size_t)r * O + o];
    }
    g_cS[ch * O + o] = s;
    g_cSS[ch * O + o] = ss;
}

__global__ void k_edge_stats(const float* __restrict__ g, const float* __restrict__ bet, int O) {
    int o = blockIdx.x * blockDim.x + threadIdx.x;
    if (o >= O) return;
    double s = 0.0, ss = 0.0;
    for (int ch = 0; ch < NCHUNK; ch++) { s += (double)g_cS[ch * O + o]; ss += (double)g_cSS[ch * O + o]; }
    double cnt = (double)BB * NN * KNN;
    double m = s / cnt;
    double var = ss / cnt - m * m;
    float sc = g[o] * rsqrtf((float)var + EPSV);
    g_scale[o] = sc;
    g_bias[o]  = bet[o] - (float)m * sc;
}

__global__ void k_bn_lrelu(int outOff, int O, int total) {
    int i = blockIdx.x * blockDim.x + threadIdx.x;
    if (i >= total) return;
    int o = i % O;
    size_t row = (size_t)(i / O);
    size_t p = row * CSTR + outOff + o;
    float v = g_F[p] * g_scale[o] + g_bias[o];
    g_F[p] = v > 0.f ? v : 0.2f * v;
}

// h stats: per-column sum/sumsq (over b,n) and per-(b,col) max
__global__ void k_ht_chunk() {
    int o = blockIdx.x * blockDim.x + threadIdx.x;
    int ch = blockIdx.y;
    if (o >= 2048) return;
    int r0 = ch * ROWS_PER_CHUNK;
    float s = 0.f, ss = 0.f, mx = -INFINITY;
    for (int r = r0; r < r0 + ROWS_PER_CHUNK; r++) {
        float v = g_HT[(size_t)r * 2048 + o];
        s += v; ss += v * v; mx = fmaxf(mx, v);
    }
    g_cS[ch * 2048 + o] = s;
    g_cSS[ch * 2048 + o] = ss;
    g_cMax[ch * 2048 + o] = mx;
}

__global__ void k_ht_final(const float* __restrict__ g5, const float* __restrict__ b5) {
    int o = blockIdx.x * blockDim.x + threadIdx.x;
    if (o >= 2048) return;
    double s = 0.0, ss = 0.0;
    float mb[BB];
#pragma unroll
    for (int b = 0; b < BB; b++) mb[b] = -INFINITY;
    for (int ch = 0; ch < NCHUNK; ch++) {
        s  += (double)g_cS[ch * 2048 + o];
        ss += (double)g_cSS[ch * 2048 + o];
        float m = g_cMax[ch * 2048 + o];
        int b = ch >> 3;
        mb[b] = fmaxf(mb[b], m);
    }
    double cnt = (double)(BB * NN);
    double md = s / cnt;
    float var = (float)(ss / cnt - md * md);
    float sc = g5[o] * rsqrtf(var + EPSV);
    float bs = b5[o] - (float)md * sc;
#pragma unroll
    for (int b = 0; b < BB; b++) {
        float v = mb[b] * sc + bs;
        g_p[b * 2048 + o] = v > 0.f ? v : 0.2f * v;
    }
}

// FC + bias + BN(over batch of 4) + relu.  inB!=null => input is concat [inA(CA) ; inB(CB)]
__global__ void k_fc_bn(const float* __restrict__ W, const float* __restrict__ wb,
                        const float* __restrict__ inA, int CA,
                        const float* __restrict__ inB, int CB,
                        const float* __restrict__ g, const float* __restrict__ bet,
                        float* __restrict__ out, int O)
{
    int o = blockIdx.x;
    int Cin = CA + CB;
    const float* w = W + (size_t)o * Cin;
    float a0 = 0.f, a1 = 0.f, a2 = 0.f, a3 = 0.f;
    for (int c = threadIdx.x; c < Cin; c += blockDim.x) {
        float wv = w[c];
        float x0, x1, x2, x3;
        if (c < CA) {
            x0 = inA[c]; x1 = inA[CA + c]; x2 = inA[2 * CA + c]; x3 = inA[3 * CA + c];
        } else {
            int cc = c - CA;
            x0 = inB[cc]; x1 = inB[CB + cc]; x2 = inB[2 * CB + cc]; x3 = inB[3 * CB + cc];
        }
        a0 += wv * x0; a1 += wv * x1; a2 += wv * x2; a3 += wv * x3;
    }
    __shared__ float sm[4][256];
    sm[0][threadIdx.x] = a0; sm[1][threadIdx.x] = a1;
    sm[2][threadIdx.x] = a2; sm[3][threadIdx.x] = a3;
    __syncthreads();
    for (int st = 128; st > 0; st >>= 1) {
        if (threadIdx.x < st) {
#pragma unroll
            for (int b = 0; b < 4; b++) sm[b][threadIdx.x] += sm[b][threadIdx.x + st];
        }
        __syncthreads();
    }
    if (threadIdx.x == 0) {
        float y[4];
#pragma unroll
        for (int b = 0; b < 4; b++) y[b] = sm[b][0] + wb[o];
        float m = (y[0] + y[1] + y[2] + y[3]) * 0.25f;
        float var = 0.f;
#pragma unroll
        for (int b = 0; b < 4; b++) { float d = y[b] - m; var += d * d; }
        var *= 0.25f;
        float sc = g[o] * rsqrtf(var + EPSV);
#pragma unroll
        for (int b = 0; b < 4; b++) {
            float z = (y[b] - m) * sc + bet[o];
            out[b * O + o] = z > 0.f ? z : 0.f;
        }
    }
}

__global__ void k_fc_out(const float* __restrict__ W, const float* __restrict__ wb,
                         float* __restrict__ out)
{
    int o = blockIdx.x;
    const float* w = W + (size_t)o * 4096;
    float a0 = 0.f, a1 = 0.f, a2 = 0.f, a3 = 0.f;
    for (int c = threadIdx.x; c < 4096; c += blockDim.x) {
        float wv = w[c];
        a0 += wv * g_z7[c];
        a1 += wv * g_z7[4096 + c];
        a2 += wv * g_z7[2 * 4096 + c];
        a3 += wv * g_z7[3 * 4096 + c];
    }
    __shared__ float sm[4][256];
    sm[0][threadIdx.x] = a0; sm[1][threadIdx.x] = a1;
    sm[2][threadIdx.x] = a2; sm[3][threadIdx.x] = a3;
    __syncthreads();
    for (int st = 128; st > 0; st >>= 1) {
        if (threadIdx.x < st) {
#pragma unroll
            for (int b = 0; b < 4; b++) sm[b][threadIdx.x] += sm[b][threadIdx.x + st];
        }
        __syncthreads();
    }
    if (threadIdx.x == 0) {
#pragma unroll
        for (int b = 0; b < 4; b++) {
            out[b * 400 + o] = tanhf(sm[b][0] + wb[o]);
        }
    }
}

// ---------------- launch ----------------
extern "C" void kernel_launch(void* const* d_in, const int* in_sizes, int n_in,
                              void* d_out, int out_size) {
    (void)in_sizes; (void)n_in; (void)out_size;
    const float* x   = (const float*)d_in[0];
    const float* w1  = (const float*)d_in[1];
    const float* g1  = (const float*)d_in[2];
    const float* b1  = (const float*)d_in[3];
    const float* w2  = (const float*)d_in[4];
    const float* g2  = (const float*)d_in[5];
    const float* b2  = (const float*)d_in[6];
    const float* w3  = (const float*)d_in[7];
    const float* g3  = (const float*)d_in[8];
    const float* b3  = (const float*)d_in[9];
    const float* w4  = (const float*)d_in[10];
    const float* g4  = (const float*)d_in[11];
    const float* b4  = (const float*)d_in[12];
    const float* w5  = (const float*)d_in[13];
    const float* g5  = (const float*)d_in[14];
    const float* b5  = (const float*)d_in[15];
    const float* w6  = (const float*)d_in[16];
    const float* wb6 = (const float*)d_in[17];
    const float* g6  = (const float*)d_in[18];
    const float* b6  = (const float*)d_in[19];
    const float* w7  = (const float*)d_in[20];
    const float* wb7 = (const float*)d_in[21];
    const float* g7  = (const float*)d_in[22];
    const float* b7  = (const float*)d_in[23];
    const float* w8  = (const float*)d_in[24];
    const float* wb8 = (const float*)d_in[25];
    float* out = (float*)d_out;

    float *pF, *pD, *pU, *pV, *pHT, *px2, *pWd, *pp, *pz6, *pz7;
    cudaGetSymbolAddress((void**)&pF,  g_F);
    cudaGetSymbolAddress((void**)&pD,  g_D);
    cudaGetSymbolAddress((void**)&pU,  g_U);
    cudaGetSymbolAddress((void**)&pV,  g_V);
    cudaGetSymbolAddress((void**)&pHT, g_HT);
    cudaGetSymbolAddress((void**)&px2, g_x2);
    cudaGetSymbolAddress((void**)&pWd, g_Wd);
    cudaGetSymbolAddress((void**)&pp,  g_p);
    cudaGetSymbolAddress((void**)&pz6, g_z6);
    cudaGetSymbolAddress((void**)&pz7, g_z7);

    dim3 thrS(16, 16);

    k_transpose_in<<<(BB * NN + 255) / 256, 256>>>(x);

    struct Layer { int inOff, C, outOff, O; const float *w, *g, *bet; };
    Layer L[4] = {
        {0,   3,   3,   64,  w1, g1, b1},
        {3,   64,  67,  128, w2, g2, b2},
        {67,  128, 195, 256, w3, g3, b3},
        {195, 256, 451, 512, w4, g4, b4},
    };

    for (int l = 0; l < 4; l++) {
        int inOff = L[l].inOff, C = L[l].C, outOff = L[l].outOff, O = L[l].O;
        const float* w = L[l].w;

        k_sqnorm<<<(BB * NN + 255) / 256, 256>>>(inOff, C);

        // pairwise distances — fast f32x2 kernel (single change this round)
        sgemm_dist_128<<<dim3(NN / 128, NN / 128, BB), 256>>>(
            pF + inOff, CSTR, (size_t)NN * CSTR,
            pD, NN, (size_t)NN * NN,
            C, px2);

        // exact top-20 selection (radix, lowest-index tie-break)
        k_select<<<BB * NN, 256>>>();

        k_wdiff<<<(O * C + 255) / 256, 256>>>(w, C, O);

        if (O >= 128) {
            sgemm_nt_128<<<dim3(O / 128, NN / 128, BB), 256>>>(
                pF + inOff, CSTR, (size_t)NN * CSTR,
                w, 2 * C, 0,
                pU, O, (size_t)NN * O,
                NN, O, C);
            sgemm_nt_128<<<dim3(O / 128, NN / 128, BB), 256>>>(
                pF + inOff, CSTR, (size_t)NN * CSTR,
                pWd, C, 0,
                pV, O, (size_t)NN * O,
                NN, O, C);
        } else {
            sgemm_nt<<<dim3((O + 63) / 64, NN / 64, BB), thrS>>>(
                pF + inOff, CSTR, (size_t)NN * CSTR,
                w, 2 * C, 0,
                pU, O, (size_t)NN * O,
                NN, O, C);
            sgemm_nt<<<dim3((O + 63) / 64, NN / 64, BB), thrS>>>(
                pF + inOff, CSTR, (size_t)NN * CSTR,
                pWd, C, 0,
                pV, O, (size_t)NN * O,
                NN, O, C);
        }

        int ethreads = (O < 256) ? O : 256;
        k_edge_reduce<<<dim3(NN, BB), ethreads>>>(outOff, O);
        k_chunk_reduce<<<dim3((O + 255) / 256, NCHUNK), 256>>>(O);
        k_edge_stats<<<(O + 255) / 256, 256>>>(L[l].g, L[l].bet, O);
        int total = BB * NN * O;
        k_bn_lrelu<<<(total + 255) / 256, 256>>>(outOff, O, total);
    }

    // h^T[b][n][o] = F[b][n][:] . w5[o][:]
    sgemm_nt_128<<<dim3(2048 / 128, NN / 128, BB), 256>>>(
        pF, CSTR, (size_t)NN * CSTR,
        w5, CSTR, 0,
        pHT, 2048, (size_t)NN * 2048,
        NN, 2048, CSTR);

    k_ht_chunk<<<dim3(8, NCHUNK), 256>>>();
    k_ht_final<<<8, 256>>>(g5, b5);

    k_fc_bn<<<2048, 256>>>(w6, wb6, pp, 2048, (const float*)0, 0, g6, b6, pz6, 2048);
    k_fc_bn<<<4096, 256>>>(w7, wb7, pz6, 2048, pp, 2048, g7, b7, pz7, 4096);
    k_fc_out<<<400, 256>>>(w8, wb8, out);
}

// round 17
// speedup vs baseline: 2.3500x; 1.2866x over previous
#include <cuda_runtime.h>
#include <cuda_bf16.h>
#include <cstdint>
#include <math.h>

#define BB 4
#define NN 2048
#define KNN 20
#define CSTR 963
#define EPSV 1e-5f
#define NCHUNK 32
#define ROWS_PER_CHUNK ((BB*NN)/NCHUNK)   // 256

// ---------------- scratch (device globals; no allocation allowed) ----------------
__device__ float g_F[(size_t)BB*NN*CSTR];      // concat features, layout [b][n][c]
__device__ float g_D[(size_t)BB*NN*NN];        // pairwise distances per batch
__device__ int   g_idx[(size_t)BB*NN*KNN];     // knn indices
__device__ float g_U[(size_t)BB*NN*512];       // U[b][m][o]
__device__ float g_V[(size_t)BB*NN*512];       // V[b][n][o]
__device__ float g_pS[(size_t)BB*NN*512];      // per-(b,n) partial sums over k
__device__ float g_pSS[(size_t)BB*NN*512];     // per-(b,n) partial sumsq over k
__device__ float g_cS[NCHUNK*2048];
__device__ float g_cSS[NCHUNK*2048];
__device__ float g_cMax[NCHUNK*2048];
__device__ float g_x2[BB*NN];
__device__ float g_scale[2048];
__device__ float g_bias[2048];
__device__ float g_Wd[512*256];
__device__ float g_HT[(size_t)BB*NN*2048];     // h transposed: [b][n][o]
__device__ float g_p[BB*2048];
__device__ float g_z6[BB*2048];
__device__ float g_z7[BB*4096];

// ---------------- f32x2 helpers (Blackwell packed fp32 FMA) ----------------
__device__ __forceinline__ unsigned long long dup2(float a) {
    unsigned long long r;
    asm("mov.b64 %0, {%1, %1};" : "=l"(r) : "f"(a));
    return r;
}
__device__ __forceinline__ unsigned long long fma2(unsigned long long a,
                                                   unsigned long long b,
                                                   unsigned long long c) {
    unsigned long long d;
    asm("fma.rn.f32x2 %0, %1, %2, %3;" : "=l"(d) : "l"(a), "l"(b), "l"(c));
    return d;
}

// ---------------- mma.sync helpers (portable PTX, sm_80+) ----------------
__device__ __forceinline__ uint32_t smem_u32(const void* p) {
    uint32_t a;
    asm("{ .reg .u64 t; cvta.to.shared.u64 t, %1; cvt.u32.u64 %0, t; }"
        : "=r"(a) : "l"(p));
    return a;
}
__device__ __forceinline__ void ldsm4(uint32_t& r0, uint32_t& r1,
                                      uint32_t& r2, uint32_t& r3, uint32_t addr) {
    asm volatile("ldmatrix.sync.aligned.m8n8.x4.shared.b16 {%0,%1,%2,%3}, [%4];"
        : "=r"(r0), "=r"(r1), "=r"(r2), "=r"(r3) : "r"(addr));
}
__device__ __forceinline__ void mma16816(float* c, const uint32_t* a, const uint32_t* b) {
    asm volatile("mma.sync.aligned.m16n8k16.row.col.f32.bf16.bf16.f32 "
        "{%0,%1,%2,%3}, {%4,%5,%6,%7}, {%8,%9}, {%0,%1,%2,%3};"
        : "+f"(c[0]), "+f"(c[1]), "+f"(c[2]), "+f"(c[3])
        : "r"(a[0]), "r"(a[1]), "r"(a[2]), "r"(a[3]), "r"(b[0]), "r"(b[1]));
}

// ================== bf16x3 split-precision NT GEMM on HMMA ==================
// Used ONLY for the w5->HT GEMM (continuous downstream: max/BN/MLP — no kNN).
// C[m,n] = sum_k A[m,k]*B[n,k];  A,B fp32 split hi/lo bf16; Ah*Bh + Ah*Bl + Al*Bh.
// CTA tile 128x128, 8 warps (4m x 2n), K-chunk 32, padded smem stride 40.
#define KC 32
#define TSTR 40
__global__ __launch_bounds__(256) void mma_gemm_nt(
        const float* __restrict__ A, int lda, size_t sA,
        const float* __restrict__ B, int ldb, size_t sB,
        float* __restrict__ C, int ldc, size_t sC,
        int K)
{
    __shared__ __align__(16) __nv_bfloat16 Ah[128 * TSTR];
    __shared__ __align__(16) __nv_bfloat16 Al[128 * TSTR];
    __shared__ __align__(16) __nv_bfloat16 Bh[128 * TSTR];
    __shared__ __align__(16) __nv_bfloat16 Bl[128 * TSTR];

    int bz = blockIdx.z;
    A += (size_t)bz * sA;
    B += (size_t)bz * sB;
    C += (size_t)bz * sC;

    int tid = threadIdx.x;
    int wid = tid >> 5, lane = tid & 31;
    int wm = wid >> 1, wn = wid & 1;
    int row0 = blockIdx.y * 128, col0 = blockIdx.x * 128;

    float acc[2][8][4];
#pragma unroll
    for (int f = 0; f < 2; f++)
#pragma unroll
        for (int g = 0; g < 8; g++)
#pragma unroll
            for (int q = 0; q < 4; q++) acc[f][g][q] = 0.f;

    int nch = (K + KC - 1) / KC;
    for (int c = 0; c < nch; c++) {
        int k0 = c * KC;
#pragma unroll
        for (int i = 0; i < 16; i++) {
            int idx = tid + i * 256;
            int r = idx >> 5, kk = idx & 31;
            int gk = k0 + kk;
            float fa = (gk < K) ? A[(size_t)(row0 + r) * lda + gk] : 0.f;
            float fb = (gk < K) ? B[(size_t)(col0 + r) * ldb + gk] : 0.f;
            __nv_bfloat16 ha = __float2bfloat16(fa);
            __nv_bfloat16 la = __float2bfloat16(fa - __bfloat162float(ha));
            __nv_bfloat16 hb = __float2bfloat16(fb);
            __nv_bfloat16 lb = __float2bfloat16(fb - __bfloat162float(hb));
            Ah[r * TSTR + kk] = ha;
            Al[r * TSTR + kk] = la;
            Bh[r * TSTR + kk] = hb;
            Bl[r * TSTR + kk] = lb;
        }
        __syncthreads();

#pragma unroll
        for (int kb = 0; kb < 2; kb++) {
            uint32_t ah[2][4], al[2][4];
#pragma unroll
            for (int f = 0; f < 2; f++) {
                int arow = wm * 32 + f * 16 + (lane & 15);
                int acol = kb * 16 + (lane >> 4) * 8;
                ldsm4(ah[f][0], ah[f][1], ah[f][2], ah[f][3],
                      smem_u32(&Ah[arow * TSTR + acol]));
                ldsm4(al[f][0], al[f][1], al[f][2], al[f][3],
                      smem_u32(&Al[arow * TSTR + acol]));
            }
#pragma unroll
            for (int g = 0; g < 4; g++) {
                int brow = wn * 64 + g * 16 + (lane & 15);
                int bcol = kb * 16 + (lane >> 4) * 8;
                uint32_t bh0, bh1, bh2, bh3, bl0, bl1, bl2, bl3;
                ldsm4(bh0, bh1, bh2, bh3, smem_u32(&Bh[brow * TSTR + bcol]));
                ldsm4(bl0, bl1, bl2, bl3, smem_u32(&Bl[brow * TSTR + bcol]));
                uint32_t b0h[2] = {bh0, bh2};
                uint32_t b1h[2] = {bh1, bh3};
                uint32_t b0l[2] = {bl0, bl2};
                uint32_t b1l[2] = {bl1, bl3};
#pragma unroll
                for (int f = 0; f < 2; f++) {
                    mma16816(acc[f][2 * g],     ah[f], b0h);
                    mma16816(acc[f][2 * g + 1], ah[f], b1h);
                    mma16816(acc[f][2 * g],     ah[f], b0l);
                    mma16816(acc[f][2 * g + 1], ah[f], b1l);
                    mma16816(acc[f][2 * g],     al[f], b0h);
                    mma16816(acc[f][2 * g + 1], al[f], b1h);
                }
            }
        }
        __syncthreads();
    }

    int rbase = row0 + wm * 32 + (lane >> 2);
    int cbase = col0 + wn * 64 + (lane & 3) * 2;
#pragma unroll
    for (int f = 0; f < 2; f++) {
#pragma unroll
        for (int g = 0; g < 8; g++) {
            int rr = rbase + f * 16;
            int cc = cbase + g * 8;
            C[(size_t)rr * ldc + cc]       = acc[f][g][0];
            C[(size_t)rr * ldc + cc + 1]   = acc[f][g][1];
            C[(size_t)(rr + 8) * ldc + cc]     = acc[f][g][2];
            C[(size_t)(rr + 8) * ldc + cc + 1] = acc[f][g][3];
        }
    }
}

// ---------------- f32x2 128x128 NT SGEMM (U/V continuous-but-kNN-feeding path) -------
__global__ __launch_bounds__(256) void sgemm_nt_128(
        const float* __restrict__ A, int lda, size_t sA,
        const float* __restrict__ B, int ldb, size_t sB,
        float* __restrict__ C, int ldc, size_t sC,
        int M, int N, int K)
{
    __shared__ float As[2][16][128];
    __shared__ float Bs[2][16][128];

    int bz = blockIdx.z;
    A += (size_t)bz * sA;
    B += (size_t)bz * sB;
    C += (size_t)bz * sC;

    int tid = threadIdx.x;
    int tx = tid & 15, ty = tid >> 4;
    int row0 = blockIdx.y * 128;
    int col0 = blockIdx.x * 128;

    unsigned long long acc[8][4];
#pragma unroll
    for (int i = 0; i < 8; i++)
#pragma unroll
        for (int j = 0; j < 4; j++) acc[i][j] = 0ULL;

    int ntiles = (K + 15) >> 4;
    float ra[8], rb[8];

#pragma unroll
    for (int e = 0; e < 8; e++) {
        int idx = tid + e * 256;
        int r = idx >> 4, kk = idx & 15;
        ra[e] = (row0 + r < M && kk < K) ? A[(size_t)(row0 + r) * lda + kk] : 0.f;
        rb[e] = (col0 + r < N && kk < K) ? B[(size_t)(col0 + r) * ldb + kk] : 0.f;
    }
#pragma unroll
    for (int e = 0; e < 8; e++) {
        int idx = tid + e * 256;
        int r = idx >> 4, kk = idx & 15;
        As[0][kk][r] = ra[e];
        Bs[0][kk][r] = rb[e];
    }
    __syncthreads();

    int buf = 0;
    for (int t = 0; t < ntiles; t++) {
        int k0n = (t + 1) * 16;
        if (t + 1 < ntiles) {
#pragma unroll
            for (int e = 0; e < 8; e++) {
                int idx = tid + e * 256;
                int r = idx >> 4, kk = idx & 15;
                int gk = k0n + kk;
                ra[e] = (row0 + r < M && gk < K) ? A[(size_t)(row0 + r) * lda + gk] : 0.f;
                rb[e] = (col0 + r < N && gk < K) ? B[(size_t)(col0 + r) * ldb + gk] : 0.f;
            }
        }

#pragma unroll
        for (int kk = 0; kk < 16; kk++) {
            float4 a0 = *(const float4*)&As[buf][kk][ty * 8];
            float4 a1 = *(const float4*)&As[buf][kk][ty * 8 + 4];
            ulonglong2 bv0 = *(const ulonglong2*)&Bs[buf][kk][tx * 8];
            ulonglong2 bv1 = *(const ulonglong2*)&Bs[buf][kk][tx * 8 + 4];
            unsigned long long bp[4] = {bv0.x, bv0.y, bv1.x, bv1.y};
            float av[8] = {a0.x, a0.y, a0.z, a0.w, a1.x, a1.y, a1.z, a1.w};
#pragma unroll
            for (int i = 0; i < 8; i++) {
                unsigned long long ad = dup2(av[i]);
#pragma unroll
                for (int j = 0; j < 4; j++)
                    acc[i][j] = fma2(ad, bp[j], acc[i][j]);
            }
        }

        if (t + 1 < ntiles) {
#pragma unroll
            for (int e = 0; e < 8; e++) {
                int idx = tid + e * 256;
                int r = idx >> 4, kk = idx & 15;
                As[buf ^ 1][kk][r] = ra[e];
                Bs[buf ^ 1][kk][r] = rb[e];
            }
        }
        __syncthreads();
        buf ^= 1;
    }

#pragma unroll
    for (int i = 0; i < 8; i++) {
        int r = row0 + ty * 8 + i;
        if (r >= M) continue;
#pragma unroll
        for (int j = 0; j < 4; j++) {
            int c = col0 + tx * 8 + j * 2;
            float2 v = *(float2*)&acc[i][j];
            if (c + 1 < N) {
                *(float2*)&C[(size_t)r * ldc + c] = v;
            } else if (c < N) {
                C[(size_t)r * ldc + c] = v.x;
            }
        }
    }
}

// ---------------- distance GEMM: 128x128 f32x2 core + dist epilogue (discrete path) --
__global__ __launch_bounds__(256) void sgemm_dist_128(
        const float* __restrict__ A, int lda, size_t sA,
        float* __restrict__ C, int ldc, size_t sC,
        int K, const float* __restrict__ sq)
{
    __shared__ float As[2][16][128];
    __shared__ float Bs[2][16][128];

    int bz = blockIdx.z;
    A += (size_t)bz * sA;
    C += (size_t)bz * sC;
    const float* sqb = sq + (size_t)bz * NN;

    int tid = threadIdx.x;
    int tx = tid & 15, ty = tid >> 4;
    int row0 = blockIdx.y * 128;
    int col0 = blockIdx.x * 128;

    unsigned long long acc[8][4];
#pragma unroll
    for (int i = 0; i < 8; i++)
#pragma unroll
        for (int j = 0; j < 4; j++) acc[i][j] = 0ULL;

    int ntiles = (K + 15) >> 4;
    float ra[8], rb[8];

#pragma unroll
    for (int e = 0; e < 8; e++) {
        int idx = tid + e * 256;
        int r = idx >> 4, kk = idx & 15;
        ra[e] = (kk < K) ? A[(size_t)(row0 + r) * lda + kk] : 0.f;
        rb[e] = (kk < K) ? A[(size_t)(col0 + r) * lda + kk] : 0.f;
    }
#pragma unroll
    for (int e = 0; e < 8; e++) {
        int idx = tid + e * 256;
        int r = idx >> 4, kk = idx & 15;
        As[0][kk][r] = ra[e];
        Bs[0][kk][r] = rb[e];
    }
    __syncthreads();

    int buf = 0;
    for (int t = 0; t < ntiles; t++) {
        int k0n = (t + 1) * 16;
        if (t + 1 < ntiles) {
#pragma unroll
            for (int e = 0; e < 8; e++) {
                int idx = tid + e * 256;
                int r = idx >> 4, kk = idx & 15;
                int gk = k0n + kk;
                ra[e] = (gk < K) ? A[(size_t)(row0 + r) * lda + gk] : 0.f;
                rb[e] = (gk < K) ? A[(size_t)(col0 + r) * lda + gk] : 0.f;
            }
        }

#pragma unroll
        for (int kk = 0; kk < 16; kk++) {
            float4 a0 = *(const float4*)&As[buf][kk][ty * 8];
            float4 a1 = *(const float4*)&As[buf][kk][ty * 8 + 4];
            ulonglong2 bv0 = *(const ulonglong2*)&Bs[buf][kk][tx * 8];
            ulonglong2 bv1 = *(const ulonglong2*)&Bs[buf][kk][tx * 8 + 4];
            unsigned long long bp[4] = {bv0.x, bv0.y, bv1.x, bv1.y};
            float av[8] = {a0.x, a0.y, a0.z, a0.w, a1.x, a1.y, a1.z, a1.w};
#pragma unroll
            for (int i = 0; i < 8; i++) {
                unsigned long long ad = dup2(av[i]);
#pragma unroll
                for (int j = 0; j < 4; j++)
                    acc[i][j] = fma2(ad, bp[j], acc[i][j]);
            }
        }

        if (t + 1 < ntiles) {
#pragma unroll
            for (int e = 0; e < 8; e++) {
                int idx = tid + e * 256;
                int r = idx >> 4, kk = idx & 15;
                As[buf ^ 1][kk][r] = ra[e];
                Bs[buf ^ 1][kk][r] = rb[e];
            }
        }
        __syncthreads();
        buf ^= 1;
    }

#pragma unroll
    for (int i = 0; i < 8; i++) {
        int r = row0 + ty * 8 + i;
        float sr = sqb[r];
#pragma unroll
        for (int j = 0; j < 4; j++) {
            int c = col0 + tx * 8 + j * 2;
            float2 v = *(float2*)&acc[i][j];
            v.x = sr + sqb[c] - 2.f * v.x;
            v.y = sr + sqb[c + 1] - 2.f * v.y;
            *(float2*)&C[(size_t)r * ldc + c] = v;
        }
    }
}

// ---------------- small NT SGEMM (layer-1 U/V: O=64) ----------------
__global__ void sgemm_nt(const float* __restrict__ A, int lda, size_t sA,
                         const float* __restrict__ B, int ldb, size_t sB,
                         float* __restrict__ C, int ldc, size_t sC,
                         int M, int N, int K)
{
    __shared__ float As[16][64];
    __shared__ float Bs[16][64];
    int bz = blockIdx.z;
    A += (size_t)bz * sA;
    B += (size_t)bz * sB;
    C += (size_t)bz * sC;

    int tid = threadIdx.y * 16 + threadIdx.x;
    int row0 = blockIdx.y * 64;
    int col0 = blockIdx.x * 64;

    float acc[4][4];
#pragma unroll
    for (int i = 0; i < 4; i++)
#pragma unroll
        for (int j = 0; j < 4; j++) acc[i][j] = 0.f;

    for (int k0 = 0; k0 < K; k0 += 16) {
#pragma unroll
        for (int e = 0; e < 4; e++) {
            int idx = tid + e * 256;
            int r  = idx >> 4;
            int kk = idx & 15;
            int gk = k0 + kk;
            int gr = row0 + r;
            As[kk][r] = (gr < M && gk < K) ? A[(size_t)gr * lda + gk] : 0.f;
            int gc = col0 + r;
            Bs[kk][r] = (gc < N && gk < K) ? B[(size_t)gc * ldb + gk] : 0.f;
        }
        __syncthreads();
#pragma unroll
        for (int kk = 0; kk < 16; kk++) {
            float4 av = *(const float4*)&As[kk][threadIdx.y * 4];
            float4 bv = *(const float4*)&Bs[kk][threadIdx.x * 4];
            float a[4] = {av.x, av.y, av.z, av.w};
            float bb[4] = {bv.x, bv.y, bv.z, bv.w};
#pragma unroll
            for (int i = 0; i < 4; i++)
#pragma unroll
                for (int j = 0; j < 4; j++)
                    acc[i][j] += a[i] * bb[j];
        }
        __syncthreads();
    }

#pragma unroll
    for (int i = 0; i < 4; i++) {
        int r = row0 + threadIdx.y * 4 + i;
        if (r >= M) continue;
#pragma unroll
        for (int j = 0; j < 4; j++) {
            int c = col0 + threadIdx.x * 4 + j;
            if (c >= N) continue;
            C[(size_t)r * ldc + c] = acc[i][j];
        }
    }
}

// ---------------- helpers ----------------
__global__ void k_transpose_in(const float* __restrict__ x) {
    int i = blockIdx.x * blockDim.x + threadIdx.x;
    if (i >= BB * NN) return;
    int b = i / NN, n = i % NN;
    float* dst = g_F + (size_t)i * CSTR;
    dst[0] = x[(size_t)b * 3 * NN + 0 * NN + n];
    dst[1] = x[(size_t)b * 3 * NN + 1 * NN + n];
    dst[2] = x[(size_t)b * 3 * NN + 2 * NN + n];
}

__global__ void k_sqnorm(int off, int C) {
    int i = blockIdx.x * blockDim.x + threadIdx.x;
    if (i >= BB * NN) return;
    const float* row = g_F + (size_t)i * CSTR + off;
    float s = 0.f;
    for (int c = 0; c < C; c++) { float v = row[c]; s += v * v; }
    g_x2[i] = s;
}

__global__ void k_wdiff(const float* __restrict__ w, int C, int O) {
    int i = blockIdx.x * blockDim.x + threadIdx.x;
    if (i >= O * C) return;
    int o = i / C, c = i % C;
    g_Wd[i] = w[(size_t)o * 2 * C + C + c] - w[(size_t)o * 2 * C + c];
}

// ---------------- exact kNN selection via 3-level radix histogram ----------------
__device__ __forceinline__ unsigned scanExcl256(unsigned v, unsigned* wsum, unsigned* total) {
    int t = threadIdx.x;
    __syncthreads();
    unsigned x = v;
#pragma unroll
    for (int o = 1; o < 32; o <<= 1) {
        unsigned y = __shfl_up_sync(0xffffffffu, x, o);
        if ((t & 31) >= o) x += y;
    }
    if ((t & 31) == 31) wsum[t >> 5] = x;
    __syncthreads();
    if (t == 0) {
        unsigned acc = 0;
#pragma unroll
        for (int w = 0; w < 8; w++) { unsigned s = wsum[w]; wsum[w] = acc; acc += s; }
        *total = acc;
    }
    __syncthreads();
    return x - v + wsum[t >> 5];
}

__global__ __launch_bounds__(256) void k_select() {
    int row = blockIdx.x;
    const float* drow = g_D + (size_t)row * NN;
    __shared__ unsigned keys[NN];
    __shared__ unsigned hist[4096];
    __shared__ unsigned wsum[8];
    __shared__ unsigned stotal;
    __shared__ unsigned s_b, s_r;

    int t = threadIdx.x;
    for (int i = t; i < NN; i += 256) {
        unsigned b = __float_as_uint(drow[i]);
        keys[i] = (b & 0x80000000u) ? ~b : (b | 0x80000000u);
    }
    for (int i = t; i < 4096; i += 256) hist[i] = 0;
    __syncthreads();
    for (int i = t; i < NN; i += 256) atomicAdd(&hist[keys[i] >> 20], 1u);
    __syncthreads();

    const unsigned RK = KNN - 1;

    unsigned seg = 0;
#pragma unroll
    for (int j = 0; j < 16; j++) seg += hist[t * 16 + j];
    unsigned off = scanExcl256(seg, wsum, &stotal);
    if (seg && off <= RK && RK < off + seg) {
        unsigned cum = off;
        for (int j = 0; j < 16; j++) {
            unsigned h = hist[t * 16 + j];
            if (cum + h > RK) { s_b = t * 16 + j; s_r = RK - cum; break; }
            cum += h;
        }
    }
    __syncthreads();
    unsigned b1 = s_b, r2 = s_r;

    for (int i = t; i < 4096; i += 256) hist[i] = 0;
    __syncthreads();
    for (int i = t; i < NN; i += 256) {
        unsigned k = keys[i];
        if ((k >> 20) == b1) atomicAdd(&hist[(k >> 8) & 0xFFFu], 1u);
    }
    __syncthreads();
    seg = 0;
#pragma unroll
    for (int j = 0; j < 16; j++) seg += hist[t * 16 + j];
    off = scanExcl256(seg, wsum, &stotal);
    if (seg && off <= r2 && r2 < off + seg) {
        unsigned cum = off;
        for (int j = 0; j < 16; j++) {
            unsigned h = hist[t * 16 + j];
            if (cum + h > r2) { s_b = t * 16 + j; s_r = r2 - cum; break; }
            cum += h;
        }
    }
    __syncthreads();
    unsigned b2 = s_b, r3 = s_r;
    unsigned pfx = (b1 << 12) | b2;

    hist[t] = 0;
    __syncthreads();
    for (int i = t; i < NN; i += 256) {
        unsigned k = keys[i];
        if ((k >> 8) == pfx) atomicAdd(&hist[k & 0xFFu], 1u);
    }
    __syncthreads();
    seg = hist[t];
    off = scanExcl256(seg, wsum, &stotal);
    if (seg && off <= r3 && r3 < off + seg) s_b = t;
    __syncthreads();
    unsigned T = (pfx << 8) | s_b;

    unsigned myk[8];
    unsigned clt = 0, ceq = 0;
#pragma unroll
    for (int j = 0; j < 8; j++) {
        myk[j] = keys[t * 8 + j];
        clt += (myk[j] < T) ? 1u : 0u;
        ceq += (myk[j] == T) ? 1u : 0u;
    }
    unsigned packed = (clt << 16) | ceq;
    unsigned poff = scanExcl256(packed, wsum, &stotal);
    unsigned totLt = stotal >> 16;
    unsigned lp = poff >> 16;
    unsigned ep = poff & 0xFFFFu;
    int* out = g_idx + (size_t)row * KNN;
#pragma unroll
    for (int j = 0; j < 8; j++) {
        unsigned k = myk[j];
        if (k < T) {
            out[lp++] = t * 8 + j;
        } else if (k == T) {
            unsigned pos = totLt + ep;
            if (pos < KNN) out[pos] = t * 8 + j;
            ep++;
        }
    }
}

// gather 20 neighbor rows of U, reduce max / sum / sumsq over k
__global__ void k_edge_reduce(int outOff, int O) {
    int n = blockIdx.x, b = blockIdx.y;
    __shared__ int sidx[KNN];
    size_t row = (size_t)b * NN + n;
    if (threadIdx.x < KNN) sidx[threadIdx.x] = g_idx[row * KNN + threadIdx.x];
    __syncthreads();
    const float* Ub = g_U + (size_t)b * NN * O;
    const float* Vb = g_V + row * O;
    for (int o = threadIdx.x; o < O; o += blockDim.x) {
        float v = Vb[o];
        float mx = -INFINITY, s = 0.f, ss = 0.f;
#pragma unroll
        for (int j = 0; j < KNN; j++) {
            float u = Ub[(size_t)sidx[j] * O + o] + v;
            mx = fmaxf(mx, u);
            s += u; ss += u * u;
        }
        g_F[row * CSTR + outOff + o] = mx;
        g_pS[row * O + o]  = s;
        g_pSS[row * O + o] = ss;
    }
}

// deterministic two-stage column reductions
__global__ void k_chunk_reduce(int O) {
    int o = blockIdx.x * blockDim.x + threadIdx.x;
    int ch = blockIdx.y;
    if (o >= O) return;
    int r0 = ch * ROWS_PER_CHUNK;
    float s = 0.f, ss = 0.f;
    for (int r = r0; r < r0 + ROWS_PER_CHUNK; r++) {
        s  += g_pS[(size_t)r * O + o];
        ss += g_pSS[(size_t)r * O + o];
    }
    g_cS[ch * O + o] = s;
    g_cSS[ch * O + o] = ss;
}

__global__ void k_edge_stats(const float* __restrict__ g, const float* __restrict__ bet, int O) {
    int o = blockIdx.x * blockDim.x + threadIdx.x;
    if (o >= O) return;
    double s = 0.0, ss = 0.0;
    for (int ch = 0; ch < NCHUNK; ch++) { s += (double)g_cS[ch * O + o]; ss += (double)g_cSS[ch * O + o]; }
    double cnt = (double)BB * NN * KNN;
    double m = s / cnt;
    double var = ss / cnt - m * m;
    float sc = g[o] * rsqrtf((float)var + EPSV);
    g_scale[o] = sc;
    g_bias[o]  = bet[o] - (float)m * sc;
}

__global__ void k_bn_lrelu(int outOff, int O, int total) {
    int i = blockIdx.x * blockDim.x + threadIdx.x;
    if (i >= total) return;
    int o = i % O;
    size_t row = (size_t)(i / O);
    size_t p = row * CSTR + outOff + o;
    float v = g_F[p] * g_scale[o] + g_bias[o];
    g_F[p] = v > 0.f ? v : 0.2f * v;
}

// h stats: per-column sum/sumsq (over b,n) and per-(b,col) max
__global__ void k_ht_chunk() {
    int o = blockIdx.x * blockDim.x + threadIdx.x;
    int ch = blockIdx.y;
    if (o >= 2048) return;
    int r0 = ch * ROWS_PER_CHUNK;
    float s = 0.f, ss = 0.f, mx = -INFINITY;
    for (int r = r0; r < r0 + ROWS_PER_CHUNK; r++) {
        float v = g_HT[(size_t)r * 2048 + o];
        s += v; ss += v * v; mx = fmaxf(mx, v);
    }
    g_cS[ch * 2048 + o] = s;
    g_cSS[ch * 2048 + o] = ss;
    g_cMax[ch * 2048 + o] = mx;
}

__global__ void k_ht_final(const float* __restrict__ g5, const float* __restrict__ b5) {
    int o = blockIdx.x * blockDim.x + threadIdx.x;
    if (o >= 2048) return;
    double s = 0.0, ss = 0.0;
    float mb[BB];
#pragma unroll
    for (int b = 0; b < BB; b++) mb[b] = -INFINITY;
    for (int ch = 0; ch < NCHUNK; ch++) {
        s  += (double)g_cS[ch * 2048 + o];
        ss += (double)g_cSS[ch * 2048 + o];
        float m = g_cMax[ch * 2048 + o];
        int b = ch >> 3;
        mb[b] = fmaxf(mb[b], m);
    }
    double cnt = (double)(BB * NN);
    double md = s / cnt;
    float var = (float)(ss / cnt - md * md);
    float sc = g5[o] * rsqrtf(var + EPSV);
    float bs = b5[o] - (float)md * sc;
#pragma unroll
    for (int b = 0; b < BB; b++) {
        float v = mb[b] * sc + bs;
        g_p[b * 2048 + o] = v > 0.f ? v : 0.2f * v;
    }
}

// FC + bias + BN(over batch of 4) + relu.  inB!=null => input is concat [inA(CA) ; inB(CB)]
__global__ void k_fc_bn(const float* __restrict__ W, const float* __restrict__ wb,
                        const float* __restrict__ inA, int CA,
                        const float* __restrict__ inB, int CB,
                        const float* __restrict__ g, const float* __restrict__ bet,
                        float* __restrict__ out, int O)
{
    int o = blockIdx.x;
    int Cin = CA + CB;
    const float* w = W + (size_t)o * Cin;
    float a0 = 0.f, a1 = 0.f, a2 = 0.f, a3 = 0.f;
    for (int c = threadIdx.x; c < Cin; c += blockDim.x) {
        float wv = w[c];
        float x0, x1, x2, x3;
        if (c < CA) {
            x0 = inA[c]; x1 = inA[CA + c]; x2 = inA[2 * CA + c]; x3 = inA[3 * CA + c];
        } else {
            int cc = c - CA;
            x0 = inB[cc]; x1 = inB[CB + cc]; x2 = inB[2 * CB + cc]; x3 = inB[3 * CB + cc];
        }
        a0 += wv * x0; a1 += wv * x1; a2 += wv * x2; a3 += wv * x3;
    }
    __shared__ float sm[4][256];
    sm[0][threadIdx.x] = a0; sm[1][threadIdx.x] = a1;
    sm[2][threadIdx.x] = a2; sm[3][threadIdx.x] = a3;
    __syncthreads();
    for (int st = 128; st > 0; st >>= 1) {
        if (threadIdx.x < st) {
#pragma unroll
            for (int b = 0; b < 4; b++) sm[b][threadIdx.x] += sm[b][threadIdx.x + st];
        }
        __syncthreads();
    }
    if (threadIdx.x == 0) {
        float y[4];
#pragma unroll
        for (int b = 0; b < 4; b++) y[b] = sm[b][0] + wb[o];
        float m = (y[0] + y[1] + y[2] + y[3]) * 0.25f;
        float var = 0.f;
#pragma unroll
        for (int b = 0; b < 4; b++) { float d = y[b] - m; var += d * d; }
        var *= 0.25f;
        float sc = g[o] * rsqrtf(var + EPSV);
#pragma unroll
        for (int b = 0; b < 4; b++) {
            float z = (y[b] - m) * sc + bet[o];
            out[b * O + o] = z > 0.f ? z : 0.f;
        }
    }
}

__global__ void k_fc_out(const float* __restrict__ W, const float* __restrict__ wb,
                         float* __restrict__ out)
{
    int o = blockIdx.x;
    const float* w = W + (size_t)o * 4096;
    float a0 = 0.f, a1 = 0.f, a2 = 0.f, a3 = 0.f;
    for (int c = threadIdx.x; c < 4096; c += blockDim.x) {
        float wv = w[c];
        a0 += wv * g_z7[c];
        a1 += wv * g_z7[4096 + c];
        a2 += wv * g_z7[2 * 4096 + c];
        a3 += wv * g_z7[3 * 4096 + c];
    }
    __shared__ float sm[4][256];
    sm[0][threadIdx.x] = a0; sm[1][threadIdx.x] = a1;
    sm[2][threadIdx.x] = a2; sm[3][threadIdx.x] = a3;
    __syncthreads();
    for (int st = 128; st > 0; st >>= 1) {
        if (threadIdx.x < st) {
#pragma unroll
            for (int b = 0; b < 4; b++) sm[b][threadIdx.x] += sm[b][threadIdx.x + st];
        }
        __syncthreads();
    }
    if (threadIdx.x == 0) {
#pragma unroll
        for (int b = 0; b < 4; b++) {
            out[b * 400 + o] = tanhf(sm[b][0] + wb[o]);
        }
    }
}

// ---------------- launch ----------------
extern "C" void kernel_launch(void* const* d_in, const int* in_sizes, int n_in,
                              void* d_out, int out_size) {
    (void)in_sizes; (void)n_in; (void)out_size;
    const float* x   = (const float*)d_in[0];
    const float* w1  = (const float*)d_in[1];
    const float* g1  = (const float*)d_in[2];
    const float* b1  = (const float*)d_in[3];
    const float* w2  = (const float*)d_in[4];
    const float* g2  = (const float*)d_in[5];
    const float* b2  = (const float*)d_in[6];
    const float* w3  = (const float*)d_in[7];
    const float* g3  = (const float*)d_in[8];
    const float* b3  = (const float*)d_in[9];
    const float* w4  = (const float*)d_in[10];
    const float* g4  = (const float*)d_in[11];
    const float* b4  = (const float*)d_in[12];
    const float* w5  = (const float*)d_in[13];
    const float* g5  = (const float*)d_in[14];
    const float* b5  = (const float*)d_in[15];
    const float* w6  = (const float*)d_in[16];
    const float* wb6 = (const float*)d_in[17];
    const float* g6  = (const float*)d_in[18];
    const float* b6  = (const float*)d_in[19];
    const float* w7  = (const float*)d_in[20];
    const float* wb7 = (const float*)d_in[21];
    const float* g7  = (const float*)d_in[22];
    const float* b7  = (const float*)d_in[23];
    const float* w8  = (const float*)d_in[24];
    const float* wb8 = (const float*)d_in[25];
    float* out = (float*)d_out;

    float *pF, *pD, *pU, *pV, *pHT, *px2, *pWd, *pp, *pz6, *pz7;
    cudaGetSymbolAddress((void**)&pF,  g_F);
    cudaGetSymbolAddress((void**)&pD,  g_D);
    cudaGetSymbolAddress((void**)&pU,  g_U);
    cudaGetSymbolAddress((void**)&pV,  g_V);
    cudaGetSymbolAddress((void**)&pHT, g_HT);
    cudaGetSymbolAddress((void**)&px2, g_x2);
    cudaGetSymbolAddress((void**)&pWd, g_Wd);
    cudaGetSymbolAddress((void**)&pp,  g_p);
    cudaGetSymbolAddress((void**)&pz6, g_z6);
    cudaGetSymbolAddress((void**)&pz7, g_z7);

    dim3 thrS(16, 16);

    k_transpose_in<<<(BB * NN + 255) / 256, 256>>>(x);

    struct Layer { int inOff, C, outOff, O; const float *w, *g, *bet; };
    Layer L[4] = {
        {0,   3,   3,   64,  w1, g1, b1},
        {3,   64,  67,  128, w2, g2, b2},
        {67,  128, 195, 256, w3, g3, b3},
        {195, 256, 451, 512, w4, g4, b4},
    };

    for (int l = 0; l < 4; l++) {
        int inOff = L[l].inOff, C = L[l].C, outOff = L[l].outOff, O = L[l].O;
        const float* w = L[l].w;

        k_sqnorm<<<(BB * NN + 255) / 256, 256>>>(inOff, C);

        // pairwise distances (discrete path — unchanged f32x2 kernel)
        sgemm_dist_128<<<dim3(NN / 128, NN / 128, BB), 256>>>(
            pF + inOff, CSTR, (size_t)NN * CSTR,
            pD, NN, (size_t)NN * NN,
            C, px2);

        // exact top-20 selection (radix, lowest-index tie-break)
        k_select<<<BB * NN, 256>>>();

        k_wdiff<<<(O * C + 255) / 256, 256>>>(w, C, O);

        if (O >= 128) {
            // U/V feed the NEXT layer's kNN — keep effectively-fp32 (f32x2)
            sgemm_nt_128<<<dim3(O / 128, NN / 128, BB), 256>>>(
                pF + inOff, CSTR, (size_t)NN * CSTR,
                w, 2 * C, 0,
                pU, O, (size_t)NN * O,
                NN, O, C);
            sgemm_nt_128<<<dim3(O / 128, NN / 128, BB), 256>>>(
                pF + inOff, CSTR, (size_t)NN * CSTR,
                pWd, C, 0,
                pV, O, (size_t)NN * O,
                NN, O, C);
        } else {
            sgemm_nt<<<dim3((O + 63) / 64, NN / 64, BB), thrS>>>(
                pF + inOff, CSTR, (size_t)NN * CSTR,
                w, 2 * C, 0,
                pU, O, (size_t)NN * O,
                NN, O, C);
            sgemm_nt<<<dim3((O + 63) / 64, NN / 64, BB), thrS>>>(
                pF + inOff, CSTR, (size_t)NN * CSTR,
                pWd, C, 0,
                pV, O, (size_t)NN * O,
                NN, O, C);
        }

        int ethreads = (O < 256) ? O : 256;
        k_edge_reduce<<<dim3(NN, BB), ethreads>>>(outOff, O);
        k_chunk_reduce<<<dim3((O + 255) / 256, NCHUNK), 256>>>(O);
        k_edge_stats<<<(O + 255) / 256, 256>>>(L[l].g, L[l].bet, O);
        int total = BB * NN * O;
        k_bn_lrelu<<<(total + 255) / 256, 256>>>(outOff, O, total);
    }

    // w5->HT: continuous downstream (max/BN/MLP only) — HMMA bf16x3 tensor-core GEMM
    mma_gemm_nt<<<dim3(2048 / 128, NN / 128, BB), 256>>>(
        pF, CSTR, (size_t)NN * CSTR,
        w5, CSTR, 0,
        pHT, 2048, (size_t)NN * 2048,
        CSTR);

    k_ht_chunk<<<dim3(8, NCHUNK), 256>>>();
    k_ht_final<<<8, 256>>>(g5, b5);

    k_fc_bn<<<2048, 256>>>(w6, wb6, pp, 2048, (const float*)0, 0, g6, b6, pz6, 2048);
    k_fc_bn<<<4096, 256>>>(w7, wb7, pz6, 2048, pp, 2048, g7, b7, pz7, 4096);
    k_fc_out<<<400, 256>>>(w8, wb8, out);
}